// round 4
// baseline (speedup 1.0000x reference)
#include <cuda_runtime.h>
#include <cuda_bf16.h>
#include <math.h>
#include <stdint.h>

// ---------------- problem constants ----------------
#define Bv   16
#define Sv   256
#define Tv   2048
#define Dv   512
#define Hv   8
#define DHv  64
#define Lv   6
#define FFv  2048
#define NMv  80
#define NTOK (Bv*Sv)            // 4096 tokens

// ---------------- scratch (no allocs allowed) ----------------
__device__ float g_x   [NTOK*Dv];
__device__ float g_qkv [NTOK*3*Dv];
__device__ float g_tmp [NTOK*Dv];
__device__ float g_durh[NTOK*256];
__device__ float g_mels[NTOK*NMv];
__device__ float g_inv [NMv];
__device__ int   g_cum [Bv*Sv];
__device__ int   g_idx [Bv*Tv];
// activation splits (bf16 hi/lo)
__device__ __nv_bfloat16 g_xH [NTOK*Dv],  g_xL [NTOK*Dv];
__device__ __nv_bfloat16 g_aH [NTOK*Dv],  g_aL [NTOK*Dv];
__device__ __nv_bfloat16 g_bH [NTOK*FFv], g_bL [NTOK*FFv];
// transposed + hi/lo-split weights ([N,K] K-major, bf16)
__device__ __nv_bfloat16 g_qkvTH[Lv*3*Dv*Dv], g_qkvTL[Lv*3*Dv*Dv];
__device__ __nv_bfloat16 g_WoTH [Lv*Dv*Dv],   g_WoTL [Lv*Dv*Dv];
__device__ __nv_bfloat16 g_W1TH [Lv*FFv*Dv],  g_W1TL [Lv*FFv*Dv];
__device__ __nv_bfloat16 g_W2TH [Lv*Dv*FFv],  g_W2TL [Lv*Dv*FFv];
__device__ __nv_bfloat16 g_m1TH [FFv*Dv],     g_m1TL [FFv*Dv];
__device__ __nv_bfloat16 g_m2TH [NMv*FFv],    g_m2TL [NMv*FFv];
__device__ __nv_bfloat16 g_d1TH [256*Dv],     g_d1TL [256*Dv];

// ---------------- low-level helpers ----------------
__device__ __forceinline__ uint32_t smem_u32(const void* p) {
    uint32_t a;
    asm("{ .reg .u64 t; cvta.to.shared.u64 t, %1; cvt.u32.u64 %0, t; }" : "=r"(a) : "l"(p));
    return a;
}
__device__ __forceinline__ void ldsm4(uint32_t& a0, uint32_t& a1, uint32_t& a2,
                                      uint32_t& a3, uint32_t addr) {
    asm volatile("ldmatrix.sync.aligned.m8n8.x4.shared.b16 {%0,%1,%2,%3}, [%4];"
                 : "=r"(a0), "=r"(a1), "=r"(a2), "=r"(a3) : "r"(addr));
}
__device__ __forceinline__ void ldsm2(uint32_t& b0, uint32_t& b1, uint32_t addr) {
    asm volatile("ldmatrix.sync.aligned.m8n8.x2.shared.b16 {%0,%1}, [%2];"
                 : "=r"(b0), "=r"(b1) : "r"(addr));
}
__device__ __forceinline__ void mma_bf16(float* c, const uint32_t* a,
                                         uint32_t b0, uint32_t b1) {
    asm volatile("mma.sync.aligned.m16n8k16.row.col.f32.bf16.bf16.f32 "
                 "{%0,%1,%2,%3}, {%4,%5,%6,%7}, {%8,%9}, {%0,%1,%2,%3};"
                 : "+f"(c[0]), "+f"(c[1]), "+f"(c[2]), "+f"(c[3])
                 : "r"(a[0]), "r"(a[1]), "r"(a[2]), "r"(a[3]), "r"(b0), "r"(b1));
}
__device__ __forceinline__ void cpa16(uint32_t dst, const void* src, int sz) {
    asm volatile("cp.async.cg.shared.global [%0], [%1], 16, %2;"
                 :: "r"(dst), "l"(src), "r"(sz) : "memory");
}
#define CPA_COMMIT() asm volatile("cp.async.commit_group;" ::: "memory")
#define CPA_WAIT1()  asm volatile("cp.async.wait_group 1;" ::: "memory")

// split two fp32 into packed bf16x2 hi + bf16x2 lo
__device__ __forceinline__ void split2(float x, float y, uint32_t& hi, uint32_t& lo) {
    __nv_bfloat162 h = __floats2bfloat162_rn(x, y);
    float hx = __bfloat162float(__low2bfloat16(h));
    float hy = __bfloat162float(__high2bfloat16(h));
    __nv_bfloat162 l2 = __floats2bfloat162_rn(x - hx, y - hy);
    hi = *(uint32_t*)&h;
    lo = *(uint32_t*)&l2;
}

// ================= all-bf16 split mma.sync GEMM, cp.async 3-stage =================
// C[M,N] = (AH+AL)[M,K] @ (BH+BL)[N,K]^T (3-term) (+bias)(+relu)
// Block 128x128x64, 8 warps (warp tile 32x64). M%128==0, K%64==0.
#define TILE_  16384u                 // 128 rows * 128 B
#define STAGE_ (4u*TILE_)             // AH, AL, BH, BL = 64 KB
#define NSTG   3
#define SMEM_G (NSTG*STAGE_)          // 192 KB

template<int EPI, int OUTS>   // EPI: 0 none,1 bias,2 bias+relu; OUTS: 0 f32, 1 split bf16
__global__ void __launch_bounds__(256, 1)
mgemm_k(const __nv_bfloat16* __restrict__ AH, const __nv_bfloat16* __restrict__ AL,
        const __nv_bfloat16* __restrict__ BH, const __nv_bfloat16* __restrict__ BL,
        const float* __restrict__ bias, float* __restrict__ C,
        __nv_bfloat16* __restrict__ CH, __nv_bfloat16* __restrict__ CL,
        int M, int N, int K)
{
    extern __shared__ char smem[];
    uint32_t sb = smem_u32(smem);
    int tid = threadIdx.x, wid = tid >> 5, l = tid & 31;
    int m0 = blockIdx.y * 128, n0 = blockIdx.x * 128;
    int wm = (wid & 3) * 32, wn = (wid >> 2) * 64;
    uint32_t swz = l & 7;

    float acc[2][8][4];
    #pragma unroll
    for (int mi = 0; mi < 2; mi++)
        #pragma unroll
        for (int ni = 0; ni < 8; ni++)
            #pragma unroll
            for (int q = 0; q < 4; q++) acc[mi][ni][q] = 0.f;

    const int NT = K / 64;
    int r0 = tid >> 3, cc = tid & 7;

    // stage loader (16B cp.async x16 per thread)
    auto load_stage = [&](int s, int kt) {
        uint32_t base = sb + (uint32_t)s * STAGE_;
        int kof = kt * 64 + cc * 8;
        #pragma unroll
        for (int i = 0; i < 4; i++) {
            int row = r0 + i * 32;
            uint32_t dst = base + (uint32_t)row * 128u
                         + (uint32_t)((cc ^ (row & 7)) << 4);
            cpa16(dst,            AH + (size_t)(m0 + row) * K + kof, 16);
            cpa16(dst + TILE_,    AL + (size_t)(m0 + row) * K + kof, 16);
            int nr = n0 + row;
            int ok = (nr < N) ? 16 : 0;
            int nrc = (nr < N) ? nr : 0;
            cpa16(dst + 2*TILE_,  BH + (size_t)nrc * K + kof, ok);
            cpa16(dst + 3*TILE_,  BL + (size_t)nrc * K + kof, ok);
        }
    };

    load_stage(0, 0); CPA_COMMIT();
    load_stage(1, 1); CPA_COMMIT();

    uint32_t arow0 = (uint32_t)(wm + (l & 15)) * 128u;
    uint32_t brow0 = (uint32_t)(wn + (l & 7)) * 128u;
    uint32_t ahi = (uint32_t)(l >> 4);          // A 16B half select
    uint32_t bhi = (uint32_t)((l >> 3) & 1);    // B 16B half select

    for (int kt = 0; kt < NT; kt++) {
        CPA_WAIT1();
        __syncthreads();
        int kn = kt + 2;
        if (kn < NT) load_stage(kn % NSTG, kn);
        CPA_COMMIT();

        uint32_t bA = sb + (uint32_t)(kt % NSTG) * STAGE_;
        uint32_t bB = bA + 2u * TILE_;
        #pragma unroll
        for (int ks = 0; ks < 4; ks++) {
            uint32_t ca = ((uint32_t)(ks * 2) + ahi) ^ swz;
            uint32_t cb = ((uint32_t)(ks * 2) + bhi) ^ swz;
            uint32_t ah[2][4], al[2][4];
            #pragma unroll
            for (int mi = 0; mi < 2; mi++) {
                uint32_t ad = bA + arow0 + (uint32_t)(mi * 16 * 128) + (ca << 4);
                ldsm4(ah[mi][0], ah[mi][1], ah[mi][2], ah[mi][3], ad);
                ldsm4(al[mi][0], al[mi][1], al[mi][2], al[mi][3], ad + TILE_);
            }
            #pragma unroll
            for (int ni = 0; ni < 8; ni++) {
                uint32_t bd = bB + brow0 + (uint32_t)(ni * 8 * 128) + (cb << 4);
                uint32_t bh0, bh1, bl0, bl1;
                ldsm2(bh0, bh1, bd);
                ldsm2(bl0, bl1, bd + TILE_);
                #pragma unroll
                for (int mi = 0; mi < 2; mi++) {
                    mma_bf16(acc[mi][ni], ah[mi], bh0, bh1);
                    mma_bf16(acc[mi][ni], al[mi], bh0, bh1);
                    mma_bf16(acc[mi][ni], ah[mi], bl0, bl1);
                }
            }
        }
    }

    // epilogue
    int r_lo = l >> 2, cpair = (l & 3) * 2;
    #pragma unroll
    for (int mi = 0; mi < 2; mi++) {
        int gr0 = m0 + wm + mi * 16 + r_lo;
        #pragma unroll
        for (int ni = 0; ni < 8; ni++) {
            int gc = n0 + wn + ni * 8 + cpair;
            if (gc < N) {
                float b0 = 0.f, b1 = 0.f;
                if (EPI >= 1) { b0 = bias[gc]; b1 = bias[gc + 1]; }
                float v0 = acc[mi][ni][0] + b0, v1 = acc[mi][ni][1] + b1;
                float v2 = acc[mi][ni][2] + b0, v3 = acc[mi][ni][3] + b1;
                if (EPI == 2) {
                    v0 = fmaxf(v0, 0.f); v1 = fmaxf(v1, 0.f);
                    v2 = fmaxf(v2, 0.f); v3 = fmaxf(v3, 0.f);
                }
                if (OUTS == 0) {
                    *(float2*)(C + (size_t)gr0 * N + gc)       = make_float2(v0, v1);
                    *(float2*)(C + (size_t)(gr0 + 8) * N + gc) = make_float2(v2, v3);
                } else {
                    uint32_t h0, l0, h1, l1;
                    split2(v0, v1, h0, l0);
                    split2(v2, v3, h1, l1);
                    *(uint32_t*)(CH + (size_t)gr0 * N + gc)       = h0;
                    *(uint32_t*)(CL + (size_t)gr0 * N + gc)       = l0;
                    *(uint32_t*)(CH + (size_t)(gr0 + 8) * N + gc) = h1;
                    *(uint32_t*)(CL + (size_t)(gr0 + 8) * N + gc) = l1;
                }
            }
        }
    }
}

// ---------------- transpose + hi/lo split: in[z][R][C] fp32 -> out[z][C][R] bf16 ----
__global__ void __launch_bounds__(256)
tsplit_k(const float* __restrict__ in, __nv_bfloat16* __restrict__ outH,
         __nv_bfloat16* __restrict__ outL, int R, int C)
{
    __shared__ float t[32][33];
    size_t zo = (size_t)blockIdx.z * R * C;
    int c0 = blockIdx.x * 32, r0 = blockIdx.y * 32;
    int x = threadIdx.x, y = threadIdx.y;
    #pragma unroll
    for (int i = 0; i < 32; i += 8) {
        int r = r0 + y + i, c = c0 + x;
        if (r < R && c < C) t[y + i][x] = in[zo + (size_t)r * C + c];
    }
    __syncthreads();
    #pragma unroll
    for (int i = 0; i < 32; i += 8) {
        int c = c0 + y + i, r = r0 + x;
        if (c < C && r < R) {
            float v = t[x][y + i];
            __nv_bfloat16 h = __float2bfloat16_rn(v);
            __nv_bfloat16 lo = __float2bfloat16_rn(v - __bfloat162float(h));
            outH[zo + (size_t)c * R + r] = h;
            outL[zo + (size_t)c * R + r] = lo;
        }
    }
}

// ---------------- misc helpers ----------------
__device__ __forceinline__ float blk_sum(float v, float* sbuf) {
    __syncthreads();
    int lane = threadIdx.x & 31, w = threadIdx.x >> 5;
    #pragma unroll
    for (int o = 16; o; o >>= 1) v += __shfl_xor_sync(0xffffffffu, v, o);
    if (lane == 0) sbuf[w] = v;
    __syncthreads();
    int nw = blockDim.x >> 5;
    float r = (threadIdx.x < nw) ? sbuf[threadIdx.x] : 0.f;
    if (w == 0) {
        #pragma unroll
        for (int o = 16; o; o >>= 1) r += __shfl_xor_sync(0xffffffffu, r, o);
        if (lane == 0) sbuf[0] = r;
    }
    __syncthreads();
    return sbuf[0];
}

// ---------------- embedding + positional encoding (+split) ----------------
__global__ void __launch_bounds__(128)
embed_k(const int* __restrict__ ids, const float* __restrict__ emb,
        const float* __restrict__ pe, float* __restrict__ x,
        __nv_bfloat16* __restrict__ xH, __nv_bfloat16* __restrict__ xL)
{
    int token = blockIdx.x;
    int tid = threadIdx.x;
    int s = token % Sv;
    int id = ids[token];
    float4 e = ((const float4*)(emb + (size_t)id * Dv))[tid];
    float4 p = ((const float4*)(pe + (size_t)s * Dv))[tid];
    e.x += p.x; e.y += p.y; e.z += p.z; e.w += p.w;
    ((float4*)(x + (size_t)token * Dv))[tid] = e;
    uint32_t h0, l0, h1, l1;
    split2(e.x, e.y, h0, l0);
    split2(e.z, e.w, h1, l1);
    ((uint2*)(xH + (size_t)token * Dv))[tid] = make_uint2(h0, h1);
    ((uint2*)(xL + (size_t)token * Dv))[tid] = make_uint2(l0, l1);
}

// ---------------- fused attention (one block per (b,h), online softmax) ------
__global__ void __launch_bounds__(256)
attn_k(const float* __restrict__ qkv, const int* __restrict__ lens,
       __nv_bfloat16* __restrict__ aH, __nv_bfloat16* __restrict__ aL)
{
    extern __shared__ float sh[];
    float* Ks = sh;
    float* Vs = sh + Sv * DHv;
    int h = blockIdx.x, b = blockIdx.y;
    int t = threadIdx.x;

    const float* base = qkv + (size_t)b * Sv * (3 * Dv);
    const float4* krow = (const float4*)(base + (size_t)t * 3 * Dv + Dv     + h * DHv);
    const float4* vrow = (const float4*)(base + (size_t)t * 3 * Dv + 2 * Dv + h * DHv);
    float4* ksd = (float4*)(Ks + t * DHv);
    float4* vsd = (float4*)(Vs + t * DHv);
    #pragma unroll
    for (int i = 0; i < 16; i++) { ksd[i] = krow[i]; vsd[i] = vrow[i]; }
    __syncthreads();

    int len = lens[b];
    float4 q4[16];
    const float4* qrow = (const float4*)(base + (size_t)t * 3 * Dv + h * DHv);
    #pragma unroll
    for (int i = 0; i < 16; i++) q4[i] = qrow[i];

    float4 a4[16];
    #pragma unroll
    for (int i = 0; i < 16; i++) a4[i] = make_float4(0.f, 0.f, 0.f, 0.f);

    const float scale = 0.125f;
    float m = -1e30f, l = 0.f;

    for (int j = 0; j < len; j++) {
        const float4* kj = (const float4*)(Ks + j * DHv);
        float s = 0.f;
        #pragma unroll
        for (int i = 0; i < 16; i++) {
            float4 kv = kj[i];
            s += q4[i].x * kv.x + q4[i].y * kv.y + q4[i].z * kv.z + q4[i].w * kv.w;
        }
        s *= scale;
        if (s > m) {
            float corr = __expf(m - s);
            l *= corr;
            #pragma unroll
            for (int i = 0; i < 16; i++) {
                a4[i].x *= corr; a4[i].y *= corr; a4[i].z *= corr; a4[i].w *= corr;
            }
            m = s;
        }
        float e = __expf(s - m);
        l += e;
        const float4* vj = (const float4*)(Vs + j * DHv);
        #pragma unroll
        for (int i = 0; i < 16; i++) {
            float4 vv = vj[i];
            a4[i].x += e * vv.x; a4[i].y += e * vv.y;
            a4[i].z += e * vv.z; a4[i].w += e * vv.w;
        }
    }

    float inv = (l > 0.f) ? 1.f / l : 0.f;
    __nv_bfloat16* ahrow = aH + ((size_t)b * Sv + t) * Dv + h * DHv;
    __nv_bfloat16* alrow = aL + ((size_t)b * Sv + t) * Dv + h * DHv;
    #pragma unroll
    for (int i = 0; i < 16; i++) {
        float4 r = a4[i];
        r.x *= inv; r.y *= inv; r.z *= inv; r.w *= inv;
        uint32_t h0, l0, h1, l1;
        split2(r.x, r.y, h0, l0);
        split2(r.z, r.w, h1, l1);
        ((uint2*)ahrow)[i] = make_uint2(h0, h1);
        ((uint2*)alrow)[i] = make_uint2(l0, l1);
    }
}

// ---------------- residual add + LayerNorm (+split) ----------------
__global__ void __launch_bounds__(128)
add_ln_k(const float* __restrict__ x, const float* __restrict__ y,
         const float* __restrict__ s, const float* __restrict__ bta,
         float* __restrict__ out,
         __nv_bfloat16* __restrict__ outH, __nv_bfloat16* __restrict__ outL)
{
    __shared__ float sbuf[8];
    int row = blockIdx.x, tid = threadIdx.x;
    float4 v = ((const float4*)(x + (size_t)row * Dv))[tid];
    float4 w = ((const float4*)(y + (size_t)row * Dv))[tid];
    v.x += w.x; v.y += w.y; v.z += w.z; v.w += w.w;

    float sum = blk_sum(v.x + v.y + v.z + v.w, sbuf);
    float mean = sum * (1.f / Dv);
    float dx = v.x - mean, dy = v.y - mean, dz = v.z - mean, dw = v.w - mean;
    float var = blk_sum(dx*dx + dy*dy + dz*dz + dw*dw, sbuf) * (1.f / Dv);
    float rstd = rsqrtf(var + 1e-5f);

    float4 sv = ((const float4*)s)[tid];
    float4 bv = ((const float4*)bta)[tid];
    float4 r;
    r.x = dx * rstd * sv.x + bv.x;
    r.y = dy * rstd * sv.y + bv.y;
    r.z = dz * rstd * sv.z + bv.z;
    r.w = dw * rstd * sv.w + bv.w;
    ((float4*)(out + (size_t)row * Dv))[tid] = r;
    uint32_t h0, l0, h1, l1;
    split2(r.x, r.y, h0, l0);
    split2(r.z, r.w, h1, l1);
    ((uint2*)(outH + (size_t)row * Dv))[tid] = make_uint2(h0, h1);
    ((uint2*)(outL + (size_t)row * Dv))[tid] = make_uint2(l0, l1);
}

// ---------------- duration head ----------------
__global__ void __launch_bounds__(256)
dur_head_k(const float* __restrict__ durh, const float* __restrict__ W2,
           const float* __restrict__ b2, float* __restrict__ dur)
{
    __shared__ float sbuf[8];
    int row = blockIdx.x, tid = threadIdx.x;
    float v = durh[(size_t)row * 256 + tid] * W2[tid];
    v = blk_sum(v, sbuf);
    if (tid == 0) {
        float z = v + b2[0];
        dur[row] = (z > 20.f) ? z : log1pf(expf(z));
    }
}

// ---------------- parallel cumulative durations ----------------
__global__ void __launch_bounds__(256)
cumsum_k(const float* __restrict__ dur, int* __restrict__ cum)
{
    __shared__ int ws[8];
    int b = blockIdx.x, t = threadIdx.x;
    int lane = t & 31, w = t >> 5;
    int d = (int)rintf(dur[b * Sv + t]);
    if (d < 1) d = 1;
    int v = d;
    #pragma unroll
    for (int o = 1; o < 32; o <<= 1) {
        int u = __shfl_up_sync(0xffffffffu, v, o);
        if (lane >= o) v += u;
    }
    if (lane == 31) ws[w] = v;
    __syncthreads();
    if (t < 8) {
        int s = ws[t];
        #pragma unroll
        for (int o = 1; o < 8; o <<= 1) {
            int u = __shfl_up_sync(0x000000ffu, s, o);
            if (t >= o) s += u;
        }
        ws[t] = s;
    }
    __syncthreads();
    int off = (w > 0) ? ws[w - 1] : 0;
    cum[b * Sv + t] = v + off;
}

// ---------------- frame -> source index ----------------
__global__ void __launch_bounds__(256)
idx_k(const int* __restrict__ cum, int* __restrict__ idx)
{
    int b = blockIdx.y;
    int t = blockIdx.x * 256 + threadIdx.x;
    const int* c = cum + b * Sv;
    int total = c[Sv - 1];
    int lo = 0, hi = Sv;
    while (lo < hi) { int mid = (lo + hi) >> 1; if (c[mid] <= t) lo = mid + 1; else hi = mid; }
    int ix = lo > (Sv - 1) ? (Sv - 1) : lo;
    idx[b * Tv + t] = (t < total) ? ix : -1;
}

// ---------------- mel for invalid frames ----------------
__global__ void __launch_bounds__(256)
melinv_k(const float* __restrict__ b1, const float* __restrict__ W2,
         const float* __restrict__ b2, float* __restrict__ inv)
{
    __shared__ float sbuf[8];
    int nm = blockIdx.x, tid = threadIdx.x;
    float v = 0.f;
    for (int f = tid; f < FFv; f += 256) {
        float r = b1[f]; r = r > 0.f ? r : 0.f;
        v += r * W2[(size_t)f * NMv + nm];
    }
    v = blk_sum(v, sbuf);
    if (tid == 0) inv[nm] = v + b2[nm];
}

// ---------------- gather mel rows into [B, NM, T] ----------------
__global__ void __launch_bounds__(256)
gather_k(const int* __restrict__ idx, const float* __restrict__ mels,
         const float* __restrict__ inv, float* __restrict__ mel)
{
    int t = blockIdx.x * 256 + threadIdx.x;
    int bn = blockIdx.y;
    int b = bn / NMv, nm = bn % NMv;
    int iv = idx[b * Tv + t];
    mel[(size_t)bn * Tv + t] =
        (iv < 0) ? inv[nm] : mels[((size_t)b * Sv + iv) * NMv + nm];
}

// ---------------- host launcher ----------------
extern "C" void kernel_launch(void* const* d_in, const int* in_sizes, int n_in,
                              void* d_out, int out_size)
{
    const int*   ids    = (const int*)  d_in[0];
    const int*   lens   = (const int*)  d_in[1];
    const float* emb    = (const float*)d_in[3];
    const float* pe     = (const float*)d_in[4];
    const float* Wqkv   = (const float*)d_in[5];
    const float* bqkv   = (const float*)d_in[6];
    const float* Wo     = (const float*)d_in[7];
    const float* bo     = (const float*)d_in[8];
    const float* ln1s   = (const float*)d_in[9];
    const float* ln1b   = (const float*)d_in[10];
    const float* ln2s   = (const float*)d_in[11];
    const float* ln2b   = (const float*)d_in[12];
    const float* W1     = (const float*)d_in[13];
    const float* b1     = (const float*)d_in[14];
    const float* W2     = (const float*)d_in[15];
    const float* b2     = (const float*)d_in[16];
    const float* melW1  = (const float*)d_in[17];
    const float* melb1  = (const float*)d_in[18];
    const float* melW2  = (const float*)d_in[19];
    const float* melb2  = (const float*)d_in[20];
    const float* durW1  = (const float*)d_in[21];
    const float* durb1  = (const float*)d_in[22];
    const float* durW2  = (const float*)d_in[23];
    const float* durb2  = (const float*)d_in[24];

    float* out     = (float*)d_out;
    float* out_mel = out;
    float* out_dur = out + (size_t)Bv * NMv * Tv;
    float* out_enc = out_dur + (size_t)Bv * Sv;

    float *x, *qkv, *tmp, *durh, *mels, *inv;
    int *cum, *idxp;
    __nv_bfloat16 *xH, *xL, *aH, *aL, *bH, *bL;
    __nv_bfloat16 *qkvTH, *qkvTL, *WoTH, *WoTL, *W1TH, *W1TL, *W2TH, *W2TL;
    __nv_bfloat16 *m1TH, *m1TL, *m2TH, *m2TL, *d1TH, *d1TL;
    cudaGetSymbolAddress((void**)&x,     g_x);
    cudaGetSymbolAddress((void**)&qkv,   g_qkv);
    cudaGetSymbolAddress((void**)&tmp,   g_tmp);
    cudaGetSymbolAddress((void**)&durh,  g_durh);
    cudaGetSymbolAddress((void**)&mels,  g_mels);
    cudaGetSymbolAddress((void**)&inv,   g_inv);
    cudaGetSymbolAddress((void**)&cum,   g_cum);
    cudaGetSymbolAddress((void**)&idxp,  g_idx);
    cudaGetSymbolAddress((void**)&xH,    g_xH);
    cudaGetSymbolAddress((void**)&xL,    g_xL);
    cudaGetSymbolAddress((void**)&aH,    g_aH);
    cudaGetSymbolAddress((void**)&aL,    g_aL);
    cudaGetSymbolAddress((void**)&bH,    g_bH);
    cudaGetSymbolAddress((void**)&bL,    g_bL);
    cudaGetSymbolAddress((void**)&qkvTH, g_qkvTH);
    cudaGetSymbolAddress((void**)&qkvTL, g_qkvTL);
    cudaGetSymbolAddress((void**)&WoTH,  g_WoTH);
    cudaGetSymbolAddress((void**)&WoTL,  g_WoTL);
    cudaGetSymbolAddress((void**)&W1TH,  g_W1TH);
    cudaGetSymbolAddress((void**)&W1TL,  g_W1TL);
    cudaGetSymbolAddress((void**)&W2TH,  g_W2TH);
    cudaGetSymbolAddress((void**)&W2TL,  g_W2TL);
    cudaGetSymbolAddress((void**)&m1TH,  g_m1TH);
    cudaGetSymbolAddress((void**)&m1TL,  g_m1TL);
    cudaGetSymbolAddress((void**)&m2TH,  g_m2TH);
    cudaGetSymbolAddress((void**)&m2TL,  g_m2TL);
    cudaGetSymbolAddress((void**)&d1TH,  g_d1TH);
    cudaGetSymbolAddress((void**)&d1TL,  g_d1TL);

    const int attn_smem = 2 * Sv * DHv * (int)sizeof(float);
    cudaFuncSetAttribute(attn_k, cudaFuncAttributeMaxDynamicSharedMemorySize, attn_smem);
    cudaFuncSetAttribute(mgemm_k<1,0>, cudaFuncAttributeMaxDynamicSharedMemorySize, SMEM_G);
    cudaFuncSetAttribute(mgemm_k<2,0>, cudaFuncAttributeMaxDynamicSharedMemorySize, SMEM_G);
    cudaFuncSetAttribute(mgemm_k<2,1>, cudaFuncAttributeMaxDynamicSharedMemorySize, SMEM_G);

    dim3 tb(32, 8);
    tsplit_k<<<dim3(48, 16, Lv), tb>>>(Wqkv,  qkvTH, qkvTL, Dv, 3 * Dv);
    tsplit_k<<<dim3(16, 16, Lv), tb>>>(Wo,    WoTH,  WoTL,  Dv, Dv);
    tsplit_k<<<dim3(64, 16, Lv), tb>>>(W1,    W1TH,  W1TL,  Dv, FFv);
    tsplit_k<<<dim3(16, 64, Lv), tb>>>(W2,    W2TH,  W2TL,  FFv, Dv);
    tsplit_k<<<dim3(64, 16, 1),  tb>>>(melW1, m1TH,  m1TL,  Dv, FFv);
    tsplit_k<<<dim3(3,  64, 1),  tb>>>(melW2, m2TH,  m2TL,  FFv, NMv);
    tsplit_k<<<dim3(8,  16, 1),  tb>>>(durW1, d1TH,  d1TL,  Dv, 256);

    embed_k<<<NTOK, 128>>>(ids, emb, pe, x, xH, xL);

    for (int l = 0; l < Lv; l++) {
        mgemm_k<1,0><<<dim3(12, 32), 256, SMEM_G>>>(
            xH, xL, qkvTH + (size_t)l * 3 * Dv * Dv, qkvTL + (size_t)l * 3 * Dv * Dv,
            bqkv + l * 3 * Dv, qkv, nullptr, nullptr, NTOK, 3 * Dv, Dv);
        attn_k<<<dim3(Hv, Bv), 256, attn_smem>>>(qkv, lens, aH, aL);
        mgemm_k<1,0><<<dim3(4, 32), 256, SMEM_G>>>(
            aH, aL, WoTH + (size_t)l * Dv * Dv, WoTL + (size_t)l * Dv * Dv,
            bo + l * Dv, tmp, nullptr, nullptr, NTOK, Dv, Dv);
        add_ln_k<<<NTOK, 128>>>(x, tmp, ln1s + l * Dv, ln1b + l * Dv, x, xH, xL);
        mgemm_k<2,1><<<dim3(16, 32), 256, SMEM_G>>>(
            xH, xL, W1TH + (size_t)l * FFv * Dv, W1TL + (size_t)l * FFv * Dv,
            b1 + l * FFv, nullptr, bH, bL, NTOK, FFv, Dv);
        mgemm_k<1,0><<<dim3(4, 32), 256, SMEM_G>>>(
            bH, bL, W2TH + (size_t)l * Dv * FFv, W2TL + (size_t)l * Dv * FFv,
            b2 + l * Dv, tmp, nullptr, nullptr, NTOK, Dv, FFv);
        add_ln_k<<<NTOK, 128>>>(x, tmp, ln2s + l * Dv, ln2b + l * Dv, x, xH, xL);
    }

    cudaMemcpyAsync(out_enc, x, (size_t)NTOK * Dv * sizeof(float),
                    cudaMemcpyDeviceToDevice);

    // duration head
    mgemm_k<2,0><<<dim3(2, 32), 256, SMEM_G>>>(
        xH, xL, d1TH, d1TL, durb1, durh, nullptr, nullptr, NTOK, 256, Dv);
    dur_head_k<<<NTOK, 256>>>(durh, durW2, durb2, out_dur);
    cumsum_k<<<Bv, 256>>>(out_dur, cum);

    // mel head on source tokens (gather commutes with row-wise MLP)
    mgemm_k<2,1><<<dim3(16, 32), 256, SMEM_G>>>(
        xH, xL, m1TH, m1TL, melb1, nullptr, bH, bL, NTOK, FFv, Dv);
    mgemm_k<1,0><<<dim3(1, 32), 256, SMEM_G>>>(
        bH, bL, m2TH, m2TL, melb2, mels, nullptr, nullptr, NTOK, NMv, FFv);
    melinv_k<<<NMv, 256>>>(melb1, melW2, melb2, inv);

    idx_k<<<dim3(Tv / 256, Bv), 256>>>(cum, idxp);
    gather_k<<<dim3(Tv / 256, Bv * NMv), 256>>>(idxp, mels, inv, out_mel);
}

// round 5
// speedup vs baseline: 1.1917x; 1.1917x over previous
#include <cuda_runtime.h>
#include <cuda_bf16.h>
#include <math.h>
#include <stdint.h>

// ---------------- problem constants ----------------
#define Bv   16
#define Sv   256
#define Tv   2048
#define Dv   512
#define Hv   8
#define DHv  64
#define Lv   6
#define FFv  2048
#define NMv  80
#define NTOK (Bv*Sv)            // 4096 tokens

// ---------------- scratch (no allocs allowed) ----------------
__device__ float g_x   [NTOK*Dv];
__device__ float g_qkv [NTOK*3*Dv];
__device__ float g_tmp [NTOK*Dv];
__device__ float g_durh[NTOK*256];
__device__ float g_mels[NTOK*NMv];
__device__ float g_inv [NMv];
__device__ int   g_cum [Bv*Sv];
__device__ int   g_idx [Bv*Tv];
// activation splits (bf16 hi/lo)
__device__ __nv_bfloat16 g_xH [NTOK*Dv],  g_xL [NTOK*Dv];
__device__ __nv_bfloat16 g_aH [NTOK*Dv],  g_aL [NTOK*Dv];
__device__ __nv_bfloat16 g_bH [NTOK*FFv], g_bL [NTOK*FFv];
// transposed + hi/lo-split weights ([N,K] K-major, bf16)
__device__ __nv_bfloat16 g_qkvTH[Lv*3*Dv*Dv], g_qkvTL[Lv*3*Dv*Dv];
__device__ __nv_bfloat16 g_WoTH [Lv*Dv*Dv],   g_WoTL [Lv*Dv*Dv];
__device__ __nv_bfloat16 g_W1TH [Lv*FFv*Dv],  g_W1TL [Lv*FFv*Dv];
__device__ __nv_bfloat16 g_W2TH [Lv*Dv*FFv],  g_W2TL [Lv*Dv*FFv];
__device__ __nv_bfloat16 g_m1TH [FFv*Dv],     g_m1TL [FFv*Dv];
__device__ __nv_bfloat16 g_m2TH [NMv*FFv],    g_m2TL [NMv*FFv];
__device__ __nv_bfloat16 g_d1TH [256*Dv],     g_d1TL [256*Dv];

// ---------------- low-level helpers ----------------
__device__ __forceinline__ uint32_t smem_u32(const void* p) {
    uint32_t a;
    asm("{ .reg .u64 t; cvta.to.shared.u64 t, %1; cvt.u32.u64 %0, t; }" : "=r"(a) : "l"(p));
    return a;
}
__device__ __forceinline__ void ldsm4(uint32_t& a0, uint32_t& a1, uint32_t& a2,
                                      uint32_t& a3, uint32_t addr) {
    asm volatile("ldmatrix.sync.aligned.m8n8.x4.shared.b16 {%0,%1,%2,%3}, [%4];"
                 : "=r"(a0), "=r"(a1), "=r"(a2), "=r"(a3) : "r"(addr));
}
__device__ __forceinline__ void ldsm2(uint32_t& b0, uint32_t& b1, uint32_t addr) {
    asm volatile("ldmatrix.sync.aligned.m8n8.x2.shared.b16 {%0,%1}, [%2];"
                 : "=r"(b0), "=r"(b1) : "r"(addr));
}
__device__ __forceinline__ void mma_bf16(float* c, const uint32_t* a,
                                         uint32_t b0, uint32_t b1) {
    asm volatile("mma.sync.aligned.m16n8k16.row.col.f32.bf16.bf16.f32 "
                 "{%0,%1,%2,%3}, {%4,%5,%6,%7}, {%8,%9}, {%0,%1,%2,%3};"
                 : "+f"(c[0]), "+f"(c[1]), "+f"(c[2]), "+f"(c[3])
                 : "r"(a[0]), "r"(a[1]), "r"(a[2]), "r"(a[3]), "r"(b0), "r"(b1));
}
// split two fp32 into packed bf16x2 hi + bf16x2 lo
__device__ __forceinline__ void split2(float x, float y, uint32_t& hi, uint32_t& lo) {
    __nv_bfloat162 h = __floats2bfloat162_rn(x, y);
    float hx = __bfloat162float(__low2bfloat16(h));
    float hy = __bfloat162float(__high2bfloat16(h));
    __nv_bfloat162 l2 = __floats2bfloat162_rn(x - hx, y - hy);
    hi = *(uint32_t*)&h;
    lo = *(uint32_t*)&l2;
}

// ================= split-bf16 mma.sync GEMM (R3 mainloop, bf16 inputs) ==========
// C[M,N] = (AH+AL)[M,K] @ (BH+BL)[N,K]^T (3-term) (+bias)(+relu)
// Block 128x128x32, 8 warps (warp tile 32x64). M%128==0, K%32==0. N guarded (even).
#define RSB     80u                      // smem row stride bytes (64B data + 16B pad)
#define TILE_B  (128u*RSB)               // 10240 B
#define STAGE_B (4u*TILE_B)              // A_hi, A_lo, B_hi, B_lo
#define SMEM_GEMM (2u*STAGE_B)           // 81920 B

template<int EPI, int OUTS>  // EPI: 0 none,1 bias,2 bias+relu; OUTS: 0 f32, 1 split bf16
__global__ void __launch_bounds__(256, 1)
mgemm_k(const __nv_bfloat16* __restrict__ AH, const __nv_bfloat16* __restrict__ AL,
        const __nv_bfloat16* __restrict__ BtH, const __nv_bfloat16* __restrict__ BtL,
        const float* __restrict__ bias, float* __restrict__ C,
        __nv_bfloat16* __restrict__ CH, __nv_bfloat16* __restrict__ CL,
        int M, int N, int K)
{
    extern __shared__ char smem[];
    uint32_t sb = smem_u32(smem);
    int tid = threadIdx.x, wid = tid >> 5, l = tid & 31;
    int m0 = blockIdx.y * 128, n0 = blockIdx.x * 128;
    int wm = (wid & 3) * 32, wn = (wid >> 2) * 64;

    float acc[2][8][4];
    #pragma unroll
    for (int mi = 0; mi < 2; mi++)
        #pragma unroll
        for (int ni = 0; ni < 8; ni++)
            #pragma unroll
            for (int q = 0; q < 4; q++) acc[mi][ni][q] = 0.f;

    int ar_ = tid >> 3, ac_ = tid & 7;    // A tile coords (32 rows x 8 col-groups)
    int br_ = tid >> 2, bc_ = tid & 3;    // B tile coords (64 rows x 4 col-groups)

    uint2 arh[4], arl[4];
    uint4 brh[2], brl[2];

    const int NT = K / 32;

    // ---- prefetch tile 0 ----
    {
        int k0 = 0;
        #pragma unroll
        for (int i = 0; i < 4; i++) {
            size_t off = (size_t)(m0 + ar_ + i * 32) * K + k0 + ac_ * 4;
            arh[i] = *(const uint2*)(AH + off);
            arl[i] = *(const uint2*)(AL + off);
        }
        #pragma unroll
        for (int i = 0; i < 2; i++) {
            int r = br_ + i * 64;
            if (n0 + r < N) {
                size_t off = (size_t)(n0 + r) * K + k0 + bc_ * 8;
                brh[i] = *(const uint4*)(BtH + off);
                brl[i] = *(const uint4*)(BtL + off);
            } else { brh[i] = make_uint4(0,0,0,0); brl[i] = make_uint4(0,0,0,0); }
        }
    }
    // ---- store tile 0 ----
    {
        #pragma unroll
        for (int i = 0; i < 4; i++) {
            uint32_t off = (uint32_t)(ar_ + i * 32) * RSB + ac_ * 8u;
            *(uint2*)(smem + off)          = arh[i];
            *(uint2*)(smem + TILE_B + off) = arl[i];
        }
        #pragma unroll
        for (int i = 0; i < 2; i++) {
            uint32_t off = (uint32_t)(br_ + i * 64) * RSB + bc_ * 16u;
            *(uint4*)(smem + 2 * TILE_B + off) = brh[i];
            *(uint4*)(smem + 3 * TILE_B + off) = brl[i];
        }
    }
    __syncthreads();

    uint32_t aoff = (uint32_t)(wm + (l & 15)) * RSB + (uint32_t)(l >> 4) * 16u;
    uint32_t boff = (uint32_t)(wn + (l & 7)) * RSB + (uint32_t)((l >> 3) & 1) * 16u;

    for (int kt = 0; kt < NT; kt++) {
        int s = kt & 1;
        // prefetch next tile into registers
        if (kt + 1 < NT) {
            int k0 = (kt + 1) * 32;
            #pragma unroll
            for (int i = 0; i < 4; i++) {
                size_t off = (size_t)(m0 + ar_ + i * 32) * K + k0 + ac_ * 4;
                arh[i] = *(const uint2*)(AH + off);
                arl[i] = *(const uint2*)(AL + off);
            }
            #pragma unroll
            for (int i = 0; i < 2; i++) {
                int r = br_ + i * 64;
                if (n0 + r < N) {
                    size_t off = (size_t)(n0 + r) * K + k0 + bc_ * 8;
                    brh[i] = *(const uint4*)(BtH + off);
                    brl[i] = *(const uint4*)(BtL + off);
                } else { brh[i] = make_uint4(0,0,0,0); brl[i] = make_uint4(0,0,0,0); }
            }
        }
        // compute on stage s
        {
            uint32_t aH_ = sb + (uint32_t)s * STAGE_B;
            uint32_t aL_ = aH_ + TILE_B;
            uint32_t bH_ = aH_ + 2 * TILE_B;
            uint32_t bL_ = aH_ + 3 * TILE_B;
            #pragma unroll
            for (int ks = 0; ks < 2; ks++) {
                uint32_t ah[2][4], al[2][4];
                #pragma unroll
                for (int mi = 0; mi < 2; mi++) {
                    uint32_t ad = aoff + (uint32_t)mi * 16u * RSB + (uint32_t)ks * 32u;
                    ldsm4(ah[mi][0], ah[mi][1], ah[mi][2], ah[mi][3], aH_ + ad);
                    ldsm4(al[mi][0], al[mi][1], al[mi][2], al[mi][3], aL_ + ad);
                }
                #pragma unroll
                for (int ni = 0; ni < 8; ni++) {
                    uint32_t bd = boff + (uint32_t)ni * 8u * RSB + (uint32_t)ks * 32u;
                    uint32_t bh0, bh1, bl0, bl1;
                    ldsm2(bh0, bh1, bH_ + bd);
                    ldsm2(bl0, bl1, bL_ + bd);
                    #pragma unroll
                    for (int mi = 0; mi < 2; mi++) {
                        mma_bf16(acc[mi][ni], ah[mi], bh0, bh1);
                        mma_bf16(acc[mi][ni], al[mi], bh0, bh1);
                        mma_bf16(acc[mi][ni], ah[mi], bl0, bl1);
                    }
                }
            }
        }
        __syncthreads();
        if (kt + 1 < NT) {
            int sn = (kt + 1) & 1;
            char* dst = smem + sn * STAGE_B;
            #pragma unroll
            for (int i = 0; i < 4; i++) {
                uint32_t off = (uint32_t)(ar_ + i * 32) * RSB + ac_ * 8u;
                *(uint2*)(dst + off)          = arh[i];
                *(uint2*)(dst + TILE_B + off) = arl[i];
            }
            #pragma unroll
            for (int i = 0; i < 2; i++) {
                uint32_t off = (uint32_t)(br_ + i * 64) * RSB + bc_ * 16u;
                *(uint4*)(dst + 2 * TILE_B + off) = brh[i];
                *(uint4*)(dst + 3 * TILE_B + off) = brl[i];
            }
            __syncthreads();
        }
    }

    // epilogue
    int r_lo = l >> 2, cpair = (l & 3) * 2;
    #pragma unroll
    for (int mi = 0; mi < 2; mi++) {
        int gr0 = m0 + wm + mi * 16 + r_lo;
        #pragma unroll
        for (int ni = 0; ni < 8; ni++) {
            int gc = n0 + wn + ni * 8 + cpair;
            if (gc < N) {
                float b0 = 0.f, b1 = 0.f;
                if (EPI >= 1) { b0 = bias[gc]; b1 = bias[gc + 1]; }
                float v0 = acc[mi][ni][0] + b0, v1 = acc[mi][ni][1] + b1;
                float v2 = acc[mi][ni][2] + b0, v3 = acc[mi][ni][3] + b1;
                if (EPI == 2) {
                    v0 = fmaxf(v0, 0.f); v1 = fmaxf(v1, 0.f);
                    v2 = fmaxf(v2, 0.f); v3 = fmaxf(v3, 0.f);
                }
                if (OUTS == 0) {
                    *(float2*)(C + (size_t)gr0 * N + gc)       = make_float2(v0, v1);
                    *(float2*)(C + (size_t)(gr0 + 8) * N + gc) = make_float2(v2, v3);
                } else {
                    uint32_t h0, l0, h1, l1;
                    split2(v0, v1, h0, l0);
                    split2(v2, v3, h1, l1);
                    *(uint32_t*)(CH + (size_t)gr0 * N + gc)       = h0;
                    *(uint32_t*)(CL + (size_t)gr0 * N + gc)       = l0;
                    *(uint32_t*)(CH + (size_t)(gr0 + 8) * N + gc) = h1;
                    *(uint32_t*)(CL + (size_t)(gr0 + 8) * N + gc) = l1;
                }
            }
        }
    }
}

// ---------------- transpose + hi/lo split: in[z][R][C] fp32 -> out[z][C][R] bf16 ----
__global__ void __launch_bounds__(256)
tsplit_k(const float* __restrict__ in, __nv_bfloat16* __restrict__ outH,
         __nv_bfloat16* __restrict__ outL, int R, int C)
{
    __shared__ float t[32][33];
    size_t zo = (size_t)blockIdx.z * R * C;
    int c0 = blockIdx.x * 32, r0 = blockIdx.y * 32;
    int x = threadIdx.x, y = threadIdx.y;
    #pragma unroll
    for (int i = 0; i < 32; i += 8) {
        int r = r0 + y + i, c = c0 + x;
        if (r < R && c < C) t[y + i][x] = in[zo + (size_t)r * C + c];
    }
    __syncthreads();
    #pragma unroll
    for (int i = 0; i < 32; i += 8) {
        int c = c0 + y + i, r = r0 + x;
        if (c < C && r < R) {
            float v = t[x][y + i];
            __nv_bfloat16 h = __float2bfloat16_rn(v);
            __nv_bfloat16 lo = __float2bfloat16_rn(v - __bfloat162float(h));
            outH[zo + (size_t)c * R + r] = h;
            outL[zo + (size_t)c * R + r] = lo;
        }
    }
}

// ---------------- misc helpers ----------------
__device__ __forceinline__ float blk_sum(float v, float* sbuf) {
    __syncthreads();
    int lane = threadIdx.x & 31, w = threadIdx.x >> 5;
    #pragma unroll
    for (int o = 16; o; o >>= 1) v += __shfl_xor_sync(0xffffffffu, v, o);
    if (lane == 0) sbuf[w] = v;
    __syncthreads();
    int nw = blockDim.x >> 5;
    float r = (threadIdx.x < nw) ? sbuf[threadIdx.x] : 0.f;
    if (w == 0) {
        #pragma unroll
        for (int o = 16; o; o >>= 1) r += __shfl_xor_sync(0xffffffffu, r, o);
        if (lane == 0) sbuf[0] = r;
    }
    __syncthreads();
    return sbuf[0];
}

// ---------------- embedding + positional encoding (+split) ----------------
__global__ void __launch_bounds__(128)
embed_k(const int* __restrict__ ids, const float* __restrict__ emb,
        const float* __restrict__ pe, float* __restrict__ x,
        __nv_bfloat16* __restrict__ xH, __nv_bfloat16* __restrict__ xL)
{
    int token = blockIdx.x;
    int tid = threadIdx.x;
    int s = token % Sv;
    int id = ids[token];
    float4 e = ((const float4*)(emb + (size_t)id * Dv))[tid];
    float4 p = ((const float4*)(pe + (size_t)s * Dv))[tid];
    e.x += p.x; e.y += p.y; e.z += p.z; e.w += p.w;
    ((float4*)(x + (size_t)token * Dv))[tid] = e;
    uint32_t h0, l0, h1, l1;
    split2(e.x, e.y, h0, l0);
    split2(e.z, e.w, h1, l1);
    ((uint2*)(xH + (size_t)token * Dv))[tid] = make_uint2(h0, h1);
    ((uint2*)(xL + (size_t)token * Dv))[tid] = make_uint2(l0, l1);
}

// ---------------- fused attention (one block per (b,h), online softmax) ------
__global__ void __launch_bounds__(256)
attn_k(const float* __restrict__ qkv, const int* __restrict__ lens,
       __nv_bfloat16* __restrict__ aH, __nv_bfloat16* __restrict__ aL)
{
    extern __shared__ float sh[];
    float* Ks = sh;
    float* Vs = sh + Sv * DHv;
    int h = blockIdx.x, b = blockIdx.y;
    int t = threadIdx.x;

    const float* base = qkv + (size_t)b * Sv * (3 * Dv);
    const float4* krow = (const float4*)(base + (size_t)t * 3 * Dv + Dv     + h * DHv);
    const float4* vrow = (const float4*)(base + (size_t)t * 3 * Dv + 2 * Dv + h * DHv);
    float4* ksd = (float4*)(Ks + t * DHv);
    float4* vsd = (float4*)(Vs + t * DHv);
    #pragma unroll
    for (int i = 0; i < 16; i++) { ksd[i] = krow[i]; vsd[i] = vrow[i]; }
    __syncthreads();

    int len = lens[b];
    float4 q4[16];
    const float4* qrow = (const float4*)(base + (size_t)t * 3 * Dv + h * DHv);
    #pragma unroll
    for (int i = 0; i < 16; i++) q4[i] = qrow[i];

    float4 a4[16];
    #pragma unroll
    for (int i = 0; i < 16; i++) a4[i] = make_float4(0.f, 0.f, 0.f, 0.f);

    const float scale = 0.125f;
    float m = -1e30f, l = 0.f;

    for (int j = 0; j < len; j++) {
        const float4* kj = (const float4*)(Ks + j * DHv);
        float s = 0.f;
        #pragma unroll
        for (int i = 0; i < 16; i++) {
            float4 kv = kj[i];
            s += q4[i].x * kv.x + q4[i].y * kv.y + q4[i].z * kv.z + q4[i].w * kv.w;
        }
        s *= scale;
        if (s > m) {
            float corr = __expf(m - s);
            l *= corr;
            #pragma unroll
            for (int i = 0; i < 16; i++) {
                a4[i].x *= corr; a4[i].y *= corr; a4[i].z *= corr; a4[i].w *= corr;
            }
            m = s;
        }
        float e = __expf(s - m);
        l += e;
        const float4* vj = (const float4*)(Vs + j * DHv);
        #pragma unroll
        for (int i = 0; i < 16; i++) {
            float4 vv = vj[i];
            a4[i].x += e * vv.x; a4[i].y += e * vv.y;
            a4[i].z += e * vv.z; a4[i].w += e * vv.w;
        }
    }

    float inv = (l > 0.f) ? 1.f / l : 0.f;
    __nv_bfloat16* ahrow = aH + ((size_t)b * Sv + t) * Dv + h * DHv;
    __nv_bfloat16* alrow = aL + ((size_t)b * Sv + t) * Dv + h * DHv;
    #pragma unroll
    for (int i = 0; i < 16; i++) {
        float4 r = a4[i];
        r.x *= inv; r.y *= inv; r.z *= inv; r.w *= inv;
        uint32_t h0, l0, h1, l1;
        split2(r.x, r.y, h0, l0);
        split2(r.z, r.w, h1, l1);
        ((uint2*)ahrow)[i] = make_uint2(h0, h1);
        ((uint2*)alrow)[i] = make_uint2(l0, l1);
    }
}

// ---------------- residual add + LayerNorm (+split) ----------------
__global__ void __launch_bounds__(128)
add_ln_k(const float* __restrict__ x, const float* __restrict__ y,
         const float* __restrict__ s, const float* __restrict__ bta,
         float* __restrict__ out,
         __nv_bfloat16* __restrict__ outH, __nv_bfloat16* __restrict__ outL)
{
    __shared__ float sbuf[8];
    int row = blockIdx.x, tid = threadIdx.x;
    float4 v = ((const float4*)(x + (size_t)row * Dv))[tid];
    float4 w = ((const float4*)(y + (size_t)row * Dv))[tid];
    v.x += w.x; v.y += w.y; v.z += w.z; v.w += w.w;

    float sum = blk_sum(v.x + v.y + v.z + v.w, sbuf);
    float mean = sum * (1.f / Dv);
    float dx = v.x - mean, dy = v.y - mean, dz = v.z - mean, dw = v.w - mean;
    float var = blk_sum(dx*dx + dy*dy + dz*dz + dw*dw, sbuf) * (1.f / Dv);
    float rstd = rsqrtf(var + 1e-5f);

    float4 sv = ((const float4*)s)[tid];
    float4 bv = ((const float4*)bta)[tid];
    float4 r;
    r.x = dx * rstd * sv.x + bv.x;
    r.y = dy * rstd * sv.y + bv.y;
    r.z = dz * rstd * sv.z + bv.z;
    r.w = dw * rstd * sv.w + bv.w;
    ((float4*)(out + (size_t)row * Dv))[tid] = r;
    uint32_t h0, l0, h1, l1;
    split2(r.x, r.y, h0, l0);
    split2(r.z, r.w, h1, l1);
    ((uint2*)(outH + (size_t)row * Dv))[tid] = make_uint2(h0, h1);
    ((uint2*)(outL + (size_t)row * Dv))[tid] = make_uint2(l0, l1);
}

// ---------------- duration head ----------------
__global__ void __launch_bounds__(256)
dur_head_k(const float* __restrict__ durh, const float* __restrict__ W2,
           const float* __restrict__ b2, float* __restrict__ dur)
{
    __shared__ float sbuf[8];
    int row = blockIdx.x, tid = threadIdx.x;
    float v = durh[(size_t)row * 256 + tid] * W2[tid];
    v = blk_sum(v, sbuf);
    if (tid == 0) {
        float z = v + b2[0];
        dur[row] = (z > 20.f) ? z : log1pf(expf(z));
    }
}

// ---------------- parallel cumulative durations ----------------
__global__ void __launch_bounds__(256)
cumsum_k(const float* __restrict__ dur, int* __restrict__ cum)
{
    __shared__ int ws[8];
    int b = blockIdx.x, t = threadIdx.x;
    int lane = t & 31, w = t >> 5;
    int d = (int)rintf(dur[b * Sv + t]);
    if (d < 1) d = 1;
    int v = d;
    #pragma unroll
    for (int o = 1; o < 32; o <<= 1) {
        int u = __shfl_up_sync(0xffffffffu, v, o);
        if (lane >= o) v += u;
    }
    if (lane == 31) ws[w] = v;
    __syncthreads();
    if (t < 8) {
        int s = ws[t];
        #pragma unroll
        for (int o = 1; o < 8; o <<= 1) {
            int u = __shfl_up_sync(0x000000ffu, s, o);
            if (t >= o) s += u;
        }
        ws[t] = s;
    }
    __syncthreads();
    int off = (w > 0) ? ws[w - 1] : 0;
    cum[b * Sv + t] = v + off;
}

// ---------------- frame -> source index ----------------
__global__ void __launch_bounds__(256)
idx_k(const int* __restrict__ cum, int* __restrict__ idx)
{
    int b = blockIdx.y;
    int t = blockIdx.x * 256 + threadIdx.x;
    const int* c = cum + b * Sv;
    int total = c[Sv - 1];
    int lo = 0, hi = Sv;
    while (lo < hi) { int mid = (lo + hi) >> 1; if (c[mid] <= t) lo = mid + 1; else hi = mid; }
    int ix = lo > (Sv - 1) ? (Sv - 1) : lo;
    idx[b * Tv + t] = (t < total) ? ix : -1;
}

// ---------------- mel for invalid frames ----------------
__global__ void __launch_bounds__(256)
melinv_k(const float* __restrict__ b1, const float* __restrict__ W2,
         const float* __restrict__ b2, float* __restrict__ inv)
{
    __shared__ float sbuf[8];
    int nm = blockIdx.x, tid = threadIdx.x;
    float v = 0.f;
    for (int f = tid; f < FFv; f += 256) {
        float r = b1[f]; r = r > 0.f ? r : 0.f;
        v += r * W2[(size_t)f * NMv + nm];
    }
    v = blk_sum(v, sbuf);
    if (tid == 0) inv[nm] = v + b2[nm];
}

// ---------------- gather mel rows into [B, NM, T] ----------------
__global__ void __launch_bounds__(256)
gather_k(const int* __restrict__ idx, const float* __restrict__ mels,
         const float* __restrict__ inv, float* __restrict__ mel)
{
    int t = blockIdx.x * 256 + threadIdx.x;
    int bn = blockIdx.y;
    int b = bn / NMv, nm = bn % NMv;
    int iv = idx[b * Tv + t];
    mel[(size_t)bn * Tv + t] =
        (iv < 0) ? inv[nm] : mels[((size_t)b * Sv + iv) * NMv + nm];
}

// ---------------- host launcher ----------------
extern "C" void kernel_launch(void* const* d_in, const int* in_sizes, int n_in,
                              void* d_out, int out_size)
{
    const int*   ids    = (const int*)  d_in[0];
    const int*   lens   = (const int*)  d_in[1];
    const float* emb    = (const float*)d_in[3];
    const float* pe     = (const float*)d_in[4];
    const float* Wqkv   = (const float*)d_in[5];
    const float* bqkv   = (const float*)d_in[6];
    const float* Wo     = (const float*)d_in[7];
    const float* bo     = (const float*)d_in[8];
    const float* ln1s   = (const float*)d_in[9];
    const float* ln1b   = (const float*)d_in[10];
    const float* ln2s   = (const float*)d_in[11];
    const float* ln2b   = (const float*)d_in[12];
    const float* W1     = (const float*)d_in[13];
    const float* b1     = (const float*)d_in[14];
    const float* W2     = (const float*)d_in[15];
    const float* b2     = (const float*)d_in[16];
    const float* melW1  = (const float*)d_in[17];
    const float* melb1  = (const float*)d_in[18];
    const float* melW2  = (const float*)d_in[19];
    const float* melb2  = (const float*)d_in[20];
    const float* durW1  = (const float*)d_in[21];
    const float* durb1  = (const float*)d_in[22];
    const float* durW2  = (const float*)d_in[23];
    const float* durb2  = (const float*)d_in[24];

    float* out     = (float*)d_out;
    float* out_mel = out;
    float* out_dur = out + (size_t)Bv * NMv * Tv;
    float* out_enc = out_dur + (size_t)Bv * Sv;

    float *x, *qkv, *tmp, *durh, *mels, *inv;
    int *cum, *idxp;
    __nv_bfloat16 *xH, *xL, *aH, *aL, *bH, *bL;
    __nv_bfloat16 *qkvTH, *qkvTL, *WoTH, *WoTL, *W1TH, *W1TL, *W2TH, *W2TL;
    __nv_bfloat16 *m1TH, *m1TL, *m2TH, *m2TL, *d1TH, *d1TL;
    cudaGetSymbolAddress((void**)&x,     g_x);
    cudaGetSymbolAddress((void**)&qkv,   g_qkv);
    cudaGetSymbolAddress((void**)&tmp,   g_tmp);
    cudaGetSymbolAddress((void**)&durh,  g_durh);
    cudaGetSymbolAddress((void**)&mels,  g_mels);
    cudaGetSymbolAddress((void**)&inv,   g_inv);
    cudaGetSymbolAddress((void**)&cum,   g_cum);
    cudaGetSymbolAddress((void**)&idxp,  g_idx);
    cudaGetSymbolAddress((void**)&xH,    g_xH);
    cudaGetSymbolAddress((void**)&xL,    g_xL);
    cudaGetSymbolAddress((void**)&aH,    g_aH);
    cudaGetSymbolAddress((void**)&aL,    g_aL);
    cudaGetSymbolAddress((void**)&bH,    g_bH);
    cudaGetSymbolAddress((void**)&bL,    g_bL);
    cudaGetSymbolAddress((void**)&qkvTH, g_qkvTH);
    cudaGetSymbolAddress((void**)&qkvTL, g_qkvTL);
    cudaGetSymbolAddress((void**)&WoTH,  g_WoTH);
    cudaGetSymbolAddress((void**)&WoTL,  g_WoTL);
    cudaGetSymbolAddress((void**)&W1TH,  g_W1TH);
    cudaGetSymbolAddress((void**)&W1TL,  g_W1TL);
    cudaGetSymbolAddress((void**)&W2TH,  g_W2TH);
    cudaGetSymbolAddress((void**)&W2TL,  g_W2TL);
    cudaGetSymbolAddress((void**)&m1TH,  g_m1TH);
    cudaGetSymbolAddress((void**)&m1TL,  g_m1TL);
    cudaGetSymbolAddress((void**)&m2TH,  g_m2TH);
    cudaGetSymbolAddress((void**)&m2TL,  g_m2TL);
    cudaGetSymbolAddress((void**)&d1TH,  g_d1TH);
    cudaGetSymbolAddress((void**)&d1TL,  g_d1TL);

    const int attn_smem = 2 * Sv * DHv * (int)sizeof(float);
    cudaFuncSetAttribute(attn_k, cudaFuncAttributeMaxDynamicSharedMemorySize, attn_smem);
    cudaFuncSetAttribute(mgemm_k<1,0>, cudaFuncAttributeMaxDynamicSharedMemorySize, SMEM_GEMM);
    cudaFuncSetAttribute(mgemm_k<2,0>, cudaFuncAttributeMaxDynamicSharedMemorySize, SMEM_GEMM);
    cudaFuncSetAttribute(mgemm_k<2,1>, cudaFuncAttributeMaxDynamicSharedMemorySize, SMEM_GEMM);

    dim3 tb(32, 8);
    tsplit_k<<<dim3(48, 16, Lv), tb>>>(Wqkv,  qkvTH, qkvTL, Dv, 3 * Dv);
    tsplit_k<<<dim3(16, 16, Lv), tb>>>(Wo,    WoTH,  WoTL,  Dv, Dv);
    tsplit_k<<<dim3(64, 16, Lv), tb>>>(W1,    W1TH,  W1TL,  Dv, FFv);
    tsplit_k<<<dim3(16, 64, Lv), tb>>>(W2,    W2TH,  W2TL,  FFv, Dv);
    tsplit_k<<<dim3(64, 16, 1),  tb>>>(melW1, m1TH,  m1TL,  Dv, FFv);
    tsplit_k<<<dim3(3,  64, 1),  tb>>>(melW2, m2TH,  m2TL,  FFv, NMv);
    tsplit_k<<<dim3(8,  16, 1),  tb>>>(durW1, d1TH,  d1TL,  Dv, 256);

    embed_k<<<NTOK, 128>>>(ids, emb, pe, x, xH, xL);

    for (int l = 0; l < Lv; l++) {
        mgemm_k<1,0><<<dim3(12, 32), 256, SMEM_GEMM>>>(
            xH, xL, qkvTH + (size_t)l * 3 * Dv * Dv, qkvTL + (size_t)l * 3 * Dv * Dv,
            bqkv + l * 3 * Dv, qkv, nullptr, nullptr, NTOK, 3 * Dv, Dv);
        attn_k<<<dim3(Hv, Bv), 256, attn_smem>>>(qkv, lens, aH, aL);
        mgemm_k<1,0><<<dim3(4, 32), 256, SMEM_GEMM>>>(
            aH, aL, WoTH + (size_t)l * Dv * Dv, WoTL + (size_t)l * Dv * Dv,
            bo + l * Dv, tmp, nullptr, nullptr, NTOK, Dv, Dv);
        add_ln_k<<<NTOK, 128>>>(x, tmp, ln1s + l * Dv, ln1b + l * Dv, x, xH, xL);
        mgemm_k<2,1><<<dim3(16, 32), 256, SMEM_GEMM>>>(
            xH, xL, W1TH + (size_t)l * FFv * Dv, W1TL + (size_t)l * FFv * Dv,
            b1 + l * FFv, nullptr, bH, bL, NTOK, FFv, Dv);
        mgemm_k<1,0><<<dim3(4, 32), 256, SMEM_GEMM>>>(
            bH, bL, W2TH + (size_t)l * Dv * FFv, W2TL + (size_t)l * Dv * FFv,
            b2 + l * Dv, tmp, nullptr, nullptr, NTOK, Dv, FFv);
        add_ln_k<<<NTOK, 128>>>(x, tmp, ln2s + l * Dv, ln2b + l * Dv, x, xH, xL);
    }

    cudaMemcpyAsync(out_enc, x, (size_t)NTOK * Dv * sizeof(float),
                    cudaMemcpyDeviceToDevice);

    // duration head
    mgemm_k<2,0><<<dim3(2, 32), 256, SMEM_GEMM>>>(
        xH, xL, d1TH, d1TL, durb1, durh, nullptr, nullptr, NTOK, 256, Dv);
    dur_head_k<<<NTOK, 256>>>(durh, durW2, durb2, out_dur);
    cumsum_k<<<Bv, 256>>>(out_dur, cum);

    // mel head on source tokens (gather commutes with row-wise MLP)
    mgemm_k<2,1><<<dim3(16, 32), 256, SMEM_GEMM>>>(
        xH, xL, m1TH, m1TL, melb1, nullptr, bH, bL, NTOK, FFv, Dv);
    mgemm_k<1,0><<<dim3(1, 32), 256, SMEM_GEMM>>>(
        bH, bL, m2TH, m2TL, melb2, mels, nullptr, nullptr, NTOK, NMv, FFv);
    melinv_k<<<NMv, 256>>>(melb1, melW2, melb2, inv);

    idx_k<<<dim3(Tv / 256, Bv), 256>>>(cum, idxp);
    gather_k<<<dim3(Tv / 256, Bv * NMv), 256>>>(idxp, mels, inv, out_mel);
}

// round 6
// speedup vs baseline: 1.3327x; 1.1183x over previous
#include <cuda_runtime.h>
#include <cuda_bf16.h>
#include <math.h>
#include <stdint.h>

// ---------------- problem constants ----------------
#define Bv   16
#define Sv   256
#define Tv   2048
#define Dv   512
#define Hv   8
#define DHv  64
#define Lv   6
#define FFv  2048
#define NMv  80
#define NTOK (Bv*Sv)            // 4096 tokens

// ---------------- scratch (no allocs allowed) ----------------
__device__ float g_x   [NTOK*Dv];
__device__ float g_qkv [NTOK*3*Dv];
__device__ float g_attn[NTOK*Dv];
__device__ float g_tmp [NTOK*Dv];
__device__ float g_big [NTOK*FFv];
__device__ float g_durh[NTOK*256];
__device__ float g_mels[NTOK*NMv];
__device__ float g_inv [NMv];
__device__ int   g_cum [Bv*Sv];
__device__ int   g_idx [Bv*Tv];
// transposed + hi/lo-split weights ([N,K] K-major, bf16)
__device__ __nv_bfloat16 g_qkvTH[Lv*3*Dv*Dv], g_qkvTL[Lv*3*Dv*Dv];
__device__ __nv_bfloat16 g_WoTH [Lv*Dv*Dv],   g_WoTL [Lv*Dv*Dv];
__device__ __nv_bfloat16 g_W1TH [Lv*FFv*Dv],  g_W1TL [Lv*FFv*Dv];
__device__ __nv_bfloat16 g_W2TH [Lv*Dv*FFv],  g_W2TL [Lv*Dv*FFv];
__device__ __nv_bfloat16 g_m1TH [FFv*Dv],     g_m1TL [FFv*Dv];
__device__ __nv_bfloat16 g_m2TH [NMv*FFv],    g_m2TL [NMv*FFv];
__device__ __nv_bfloat16 g_d1TH [256*Dv],     g_d1TL [256*Dv];

// ---------------- low-level helpers ----------------
__device__ __forceinline__ uint32_t smem_u32(const void* p) {
    uint32_t a;
    asm("{ .reg .u64 t; cvta.to.shared.u64 t, %1; cvt.u32.u64 %0, t; }" : "=r"(a) : "l"(p));
    return a;
}
__device__ __forceinline__ void ldsm4(uint32_t& a0, uint32_t& a1, uint32_t& a2,
                                      uint32_t& a3, uint32_t addr) {
    asm volatile("ldmatrix.sync.aligned.m8n8.x4.shared.b16 {%0,%1,%2,%3}, [%4];"
                 : "=r"(a0), "=r"(a1), "=r"(a2), "=r"(a3) : "r"(addr));
}
__device__ __forceinline__ void ldsm2(uint32_t& b0, uint32_t& b1, uint32_t addr) {
    asm volatile("ldmatrix.sync.aligned.m8n8.x2.shared.b16 {%0,%1}, [%2];"
                 : "=r"(b0), "=r"(b1) : "r"(addr));
}
__device__ __forceinline__ void mma_bf16(float* c, const uint32_t* a,
                                         uint32_t b0, uint32_t b1) {
    asm volatile("mma.sync.aligned.m16n8k16.row.col.f32.bf16.bf16.f32 "
                 "{%0,%1,%2,%3}, {%4,%5,%6,%7}, {%8,%9}, {%0,%1,%2,%3};"
                 : "+f"(c[0]), "+f"(c[1]), "+f"(c[2]), "+f"(c[3])
                 : "r"(a[0]), "r"(a[1]), "r"(a[2]), "r"(a[3]), "r"(b0), "r"(b1));
}
// split two fp32 into packed bf16x2 hi + bf16x2 lo
__device__ __forceinline__ void split2(float x, float y, uint32_t& hi, uint32_t& lo) {
    __nv_bfloat162 h = __floats2bfloat162_rn(x, y);
    float hx = __bfloat162float(__low2bfloat16(h));
    float hy = __bfloat162float(__high2bfloat16(h));
    __nv_bfloat162 l2 = __floats2bfloat162_rn(x - hx, y - hy);
    hi = *(uint32_t*)&h;
    lo = *(uint32_t*)&l2;
}

// ================= split-bf16 mma.sync GEMM (R3 mainloop, templated N-tile) =====
// C[M,N] = A[M,K] @ (BtH+BtL)[N,K]^T (3-term) (+bias)(+relu)
// Block 128 x NT_ x 32, 8 warps. Warp tile 32 x (NT_/2). M%128==0, K%32==0.
#define RSB     80u                      // smem row stride bytes (64B data + 16B pad)
#define TILE_A  (128u*RSB)               // 10240 B

template<int NT_, int EPI>   // NT_ in {64,128}; EPI: 0 none, 1 bias, 2 bias+relu
__global__ void __launch_bounds__(256, 1)
mgemm_k(const float* __restrict__ A,
        const __nv_bfloat16* __restrict__ BtH,
        const __nv_bfloat16* __restrict__ BtL,
        const float* __restrict__ bias, float* __restrict__ C,
        int M, int N, int K)
{
    constexpr uint32_t TILE_BN = (uint32_t)NT_ * RSB;
    constexpr uint32_t STAGE = 2u * TILE_A + 2u * TILE_BN;
    constexpr int NI = NT_ / 16;                 // B ni count per warp
    extern __shared__ char smem[];
    uint32_t sb = smem_u32(smem);
    int tid = threadIdx.x, wid = tid >> 5, l = tid & 31;
    int m0 = blockIdx.y * 128, n0 = blockIdx.x * NT_;
    int wm = (wid & 3) * 32, wn = (wid >> 2) * (NT_ / 2);

    float acc[2][NI][4];
    #pragma unroll
    for (int mi = 0; mi < 2; mi++)
        #pragma unroll
        for (int ni = 0; ni < NI; ni++)
            #pragma unroll
            for (int q = 0; q < 4; q++) acc[mi][ni][q] = 0.f;

    int ar_ = tid >> 3, ac_ = tid & 7;    // A tile coords (32 rows x 8 col-groups)
    int br_ = tid >> 2, bc_ = tid & 3;    // B tile coords (64 rows x 4 col-groups)

    float4 ard[4];
    uint4  brh[NT_/64], brl[NT_/64];

    const int NT = K / 32;

    // ---- prefetch tile 0 ----
    {
        #pragma unroll
        for (int i = 0; i < 4; i++)
            ard[i] = *(const float4*)(A + (size_t)(m0 + ar_ + i * 32) * K + ac_ * 4);
        #pragma unroll
        for (int i = 0; i < NT_/64; i++) {
            int r = br_ + i * 64;
            if (n0 + r < N) {
                size_t off = (size_t)(n0 + r) * K + bc_ * 8;
                brh[i] = *(const uint4*)(BtH + off);
                brl[i] = *(const uint4*)(BtL + off);
            } else { brh[i] = make_uint4(0,0,0,0); brl[i] = make_uint4(0,0,0,0); }
        }
    }
    // ---- store tile 0 ----
    {
        #pragma unroll
        for (int i = 0; i < 4; i++) {
            uint32_t h0, h1, l0, l1;
            split2(ard[i].x, ard[i].y, h0, l0);
            split2(ard[i].z, ard[i].w, h1, l1);
            uint32_t off = (uint32_t)(ar_ + i * 32) * RSB + ac_ * 8u;
            *(uint2*)(smem + off)          = make_uint2(h0, h1);
            *(uint2*)(smem + TILE_A + off) = make_uint2(l0, l1);
        }
        #pragma unroll
        for (int i = 0; i < NT_/64; i++) {
            uint32_t off = (uint32_t)(br_ + i * 64) * RSB + bc_ * 16u;
            *(uint4*)(smem + 2 * TILE_A + off)           = brh[i];
            *(uint4*)(smem + 2 * TILE_A + TILE_BN + off) = brl[i];
        }
    }
    __syncthreads();

    uint32_t aoff = (uint32_t)(wm + (l & 15)) * RSB + (uint32_t)(l >> 4) * 16u;
    uint32_t boff = (uint32_t)(wn + (l & 7)) * RSB + (uint32_t)((l >> 3) & 1) * 16u;

    for (int kt = 0; kt < NT; kt++) {
        int s = kt & 1;
        // prefetch next tile into registers
        if (kt + 1 < NT) {
            int k0 = (kt + 1) * 32;
            #pragma unroll
            for (int i = 0; i < 4; i++)
                ard[i] = *(const float4*)(A + (size_t)(m0 + ar_ + i * 32) * K + k0 + ac_ * 4);
            #pragma unroll
            for (int i = 0; i < NT_/64; i++) {
                int r = br_ + i * 64;
                if (n0 + r < N) {
                    size_t off = (size_t)(n0 + r) * K + k0 + bc_ * 8;
                    brh[i] = *(const uint4*)(BtH + off);
                    brl[i] = *(const uint4*)(BtL + off);
                } else { brh[i] = make_uint4(0,0,0,0); brl[i] = make_uint4(0,0,0,0); }
            }
        }
        // compute on stage s
        {
            uint32_t aH_ = sb + (uint32_t)s * STAGE;
            uint32_t aL_ = aH_ + TILE_A;
            uint32_t bH_ = aH_ + 2 * TILE_A;
            uint32_t bL_ = bH_ + TILE_BN;
            #pragma unroll
            for (int ks = 0; ks < 2; ks++) {
                uint32_t ah[2][4], al[2][4];
                #pragma unroll
                for (int mi = 0; mi < 2; mi++) {
                    uint32_t ad = aoff + (uint32_t)mi * 16u * RSB + (uint32_t)ks * 32u;
                    ldsm4(ah[mi][0], ah[mi][1], ah[mi][2], ah[mi][3], aH_ + ad);
                    ldsm4(al[mi][0], al[mi][1], al[mi][2], al[mi][3], aL_ + ad);
                }
                #pragma unroll
                for (int ni = 0; ni < NI; ni++) {
                    uint32_t bd = boff + (uint32_t)ni * 8u * RSB + (uint32_t)ks * 32u;
                    uint32_t bh0, bh1, bl0, bl1;
                    ldsm2(bh0, bh1, bH_ + bd);
                    ldsm2(bl0, bl1, bL_ + bd);
                    #pragma unroll
                    for (int mi = 0; mi < 2; mi++) {
                        mma_bf16(acc[mi][ni], ah[mi], bh0, bh1);
                        mma_bf16(acc[mi][ni], al[mi], bh0, bh1);
                        mma_bf16(acc[mi][ni], ah[mi], bl0, bl1);
                    }
                }
            }
        }
        __syncthreads();
        if (kt + 1 < NT) {
            int sn = (kt + 1) & 1;
            char* dst = smem + (uint32_t)sn * STAGE;
            #pragma unroll
            for (int i = 0; i < 4; i++) {
                uint32_t h0, h1, l0, l1;
                split2(ard[i].x, ard[i].y, h0, l0);
                split2(ard[i].z, ard[i].w, h1, l1);
                uint32_t off = (uint32_t)(ar_ + i * 32) * RSB + ac_ * 8u;
                *(uint2*)(dst + off)          = make_uint2(h0, h1);
                *(uint2*)(dst + TILE_A + off) = make_uint2(l0, l1);
            }
            #pragma unroll
            for (int i = 0; i < NT_/64; i++) {
                uint32_t off = (uint32_t)(br_ + i * 64) * RSB + bc_ * 16u;
                *(uint4*)(dst + 2 * TILE_A + off)           = brh[i];
                *(uint4*)(dst + 2 * TILE_A + TILE_BN + off) = brl[i];
            }
            __syncthreads();
        }
    }

    // epilogue
    int r_lo = l >> 2, cpair = (l & 3) * 2;
    #pragma unroll
    for (int mi = 0; mi < 2; mi++) {
        int gr0 = m0 + wm + mi * 16 + r_lo;
        #pragma unroll
        for (int ni = 0; ni < NI; ni++) {
            int gc = n0 + wn + ni * 8 + cpair;
            if (gc < N) {
                float b0 = 0.f, b1 = 0.f;
                if (EPI >= 1) { b0 = bias[gc]; b1 = bias[gc + 1]; }
                float v0 = acc[mi][ni][0] + b0, v1 = acc[mi][ni][1] + b1;
                float v2 = acc[mi][ni][2] + b0, v3 = acc[mi][ni][3] + b1;
                if (EPI == 2) {
                    v0 = fmaxf(v0, 0.f); v1 = fmaxf(v1, 0.f);
                    v2 = fmaxf(v2, 0.f); v3 = fmaxf(v3, 0.f);
                }
                *(float2*)(C + (size_t)gr0 * N + gc)       = make_float2(v0, v1);
                *(float2*)(C + (size_t)(gr0 + 8) * N + gc) = make_float2(v2, v3);
            }
        }
    }
}

// ---------------- transpose + hi/lo split: in[z][R][C] fp32 -> out[z][C][R] bf16 ----
__global__ void __launch_bounds__(256)
tsplit_k(const float* __restrict__ in, __nv_bfloat16* __restrict__ outH,
         __nv_bfloat16* __restrict__ outL, int R, int C)
{
    __shared__ float t[32][33];
    size_t zo = (size_t)blockIdx.z * R * C;
    int c0 = blockIdx.x * 32, r0 = blockIdx.y * 32;
    int x = threadIdx.x, y = threadIdx.y;
    #pragma unroll
    for (int i = 0; i < 32; i += 8) {
        int r = r0 + y + i, c = c0 + x;
        if (r < R && c < C) t[y + i][x] = in[zo + (size_t)r * C + c];
    }
    __syncthreads();
    #pragma unroll
    for (int i = 0; i < 32; i += 8) {
        int c = c0 + y + i, r = r0 + x;
        if (c < C && r < R) {
            float v = t[x][y + i];
            __nv_bfloat16 h = __float2bfloat16_rn(v);
            __nv_bfloat16 lo = __float2bfloat16_rn(v - __bfloat162float(h));
            outH[zo + (size_t)c * R + r] = h;
            outL[zo + (size_t)c * R + r] = lo;
        }
    }
}

// ---------------- misc helpers ----------------
__device__ __forceinline__ float blk_sum(float v, float* sbuf) {
    __syncthreads();
    int lane = threadIdx.x & 31, w = threadIdx.x >> 5;
    #pragma unroll
    for (int o = 16; o; o >>= 1) v += __shfl_xor_sync(0xffffffffu, v, o);
    if (lane == 0) sbuf[w] = v;
    __syncthreads();
    int nw = blockDim.x >> 5;
    float r = (threadIdx.x < nw) ? sbuf[threadIdx.x] : 0.f;
    if (w == 0) {
        #pragma unroll
        for (int o = 16; o; o >>= 1) r += __shfl_xor_sync(0xffffffffu, r, o);
        if (lane == 0) sbuf[0] = r;
    }
    __syncthreads();
    return sbuf[0];
}

// ---------------- embedding + positional encoding ----------------
__global__ void __launch_bounds__(128)
embed_k(const int* __restrict__ ids, const float* __restrict__ emb,
        const float* __restrict__ pe, float* __restrict__ x)
{
    int token = blockIdx.x;
    int tid = threadIdx.x;
    int s = token % Sv;
    int id = ids[token];
    float4 e = ((const float4*)(emb + (size_t)id * Dv))[tid];
    float4 p = ((const float4*)(pe + (size_t)s * Dv))[tid];
    e.x += p.x; e.y += p.y; e.z += p.z; e.w += p.w;
    ((float4*)(x + (size_t)token * Dv))[tid] = e;
}

// ---------------- fused attention (one block per (b,h), online softmax) ------
__global__ void __launch_bounds__(256)
attn_k(const float* __restrict__ qkv, const int* __restrict__ lens,
       float* __restrict__ o)
{
    extern __shared__ float sh[];
    float* Ks = sh;
    float* Vs = sh + Sv * DHv;
    int h = blockIdx.x, b = blockIdx.y;
    int t = threadIdx.x;

    const float* base = qkv + (size_t)b * Sv * (3 * Dv);
    const float4* krow = (const float4*)(base + (size_t)t * 3 * Dv + Dv     + h * DHv);
    const float4* vrow = (const float4*)(base + (size_t)t * 3 * Dv + 2 * Dv + h * DHv);
    float4* ksd = (float4*)(Ks + t * DHv);
    float4* vsd = (float4*)(Vs + t * DHv);
    #pragma unroll
    for (int i = 0; i < 16; i++) { ksd[i] = krow[i]; vsd[i] = vrow[i]; }
    __syncthreads();

    int len = lens[b];
    float4 q4[16];
    const float4* qrow = (const float4*)(base + (size_t)t * 3 * Dv + h * DHv);
    #pragma unroll
    for (int i = 0; i < 16; i++) q4[i] = qrow[i];

    float4 a4[16];
    #pragma unroll
    for (int i = 0; i < 16; i++) a4[i] = make_float4(0.f, 0.f, 0.f, 0.f);

    const float scale = 0.125f;
    float m = -1e30f, l = 0.f;

    for (int j = 0; j < len; j++) {
        const float4* kj = (const float4*)(Ks + j * DHv);
        float s = 0.f;
        #pragma unroll
        for (int i = 0; i < 16; i++) {
            float4 kv = kj[i];
            s += q4[i].x * kv.x + q4[i].y * kv.y + q4[i].z * kv.z + q4[i].w * kv.w;
        }
        s *= scale;
        if (s > m) {
            float corr = __expf(m - s);
            l *= corr;
            #pragma unroll
            for (int i = 0; i < 16; i++) {
                a4[i].x *= corr; a4[i].y *= corr; a4[i].z *= corr; a4[i].w *= corr;
            }
            m = s;
        }
        float e = __expf(s - m);
        l += e;
        const float4* vj = (const float4*)(Vs + j * DHv);
        #pragma unroll
        for (int i = 0; i < 16; i++) {
            float4 vv = vj[i];
            a4[i].x += e * vv.x; a4[i].y += e * vv.y;
            a4[i].z += e * vv.z; a4[i].w += e * vv.w;
        }
    }

    float inv = (l > 0.f) ? 1.f / l : 0.f;
    float4* orow = (float4*)(o + ((size_t)b * Sv + t) * Dv + h * DHv);
    #pragma unroll
    for (int i = 0; i < 16; i++) {
        float4 r = a4[i];
        r.x *= inv; r.y *= inv; r.z *= inv; r.w *= inv;
        orow[i] = r;
    }
}

// ---------------- residual add + LayerNorm ----------------
__global__ void __launch_bounds__(128)
add_ln_k(const float* __restrict__ x, const float* __restrict__ y,
         const float* __restrict__ s, const float* __restrict__ bta,
         float* __restrict__ out)
{
    __shared__ float sbuf[8];
    int row = blockIdx.x, tid = threadIdx.x;
    float4 v = ((const float4*)(x + (size_t)row * Dv))[tid];
    float4 w = ((const float4*)(y + (size_t)row * Dv))[tid];
    v.x += w.x; v.y += w.y; v.z += w.z; v.w += w.w;

    float sum = blk_sum(v.x + v.y + v.z + v.w, sbuf);
    float mean = sum * (1.f / Dv);
    float dx = v.x - mean, dy = v.y - mean, dz = v.z - mean, dw = v.w - mean;
    float var = blk_sum(dx*dx + dy*dy + dz*dz + dw*dw, sbuf) * (1.f / Dv);
    float rstd = rsqrtf(var + 1e-5f);

    float4 sv = ((const float4*)s)[tid];
    float4 bv = ((const float4*)bta)[tid];
    float4 r;
    r.x = dx * rstd * sv.x + bv.x;
    r.y = dy * rstd * sv.y + bv.y;
    r.z = dz * rstd * sv.z + bv.z;
    r.w = dw * rstd * sv.w + bv.w;
    ((float4*)(out + (size_t)row * Dv))[tid] = r;
}

// ---------------- duration head ----------------
__global__ void __launch_bounds__(256)
dur_head_k(const float* __restrict__ durh, const float* __restrict__ W2,
           const float* __restrict__ b2, float* __restrict__ dur)
{
    __shared__ float sbuf[8];
    int row = blockIdx.x, tid = threadIdx.x;
    float v = durh[(size_t)row * 256 + tid] * W2[tid];
    v = blk_sum(v, sbuf);
    if (tid == 0) {
        float z = v + b2[0];
        dur[row] = (z > 20.f) ? z : log1pf(expf(z));
    }
}

// ---------------- parallel cumulative durations ----------------
__global__ void __launch_bounds__(256)
cumsum_k(const float* __restrict__ dur, int* __restrict__ cum)
{
    __shared__ int ws[8];
    int b = blockIdx.x, t = threadIdx.x;
    int lane = t & 31, w = t >> 5;
    int d = (int)rintf(dur[b * Sv + t]);
    if (d < 1) d = 1;
    int v = d;
    #pragma unroll
    for (int o = 1; o < 32; o <<= 1) {
        int u = __shfl_up_sync(0xffffffffu, v, o);
        if (lane >= o) v += u;
    }
    if (lane == 31) ws[w] = v;
    __syncthreads();
    if (t < 8) {
        int s = ws[t];
        #pragma unroll
        for (int o = 1; o < 8; o <<= 1) {
            int u = __shfl_up_sync(0x000000ffu, s, o);
            if (t >= o) s += u;
        }
        ws[t] = s;
    }
    __syncthreads();
    int off = (w > 0) ? ws[w - 1] : 0;
    cum[b * Sv + t] = v + off;
}

// ---------------- frame -> source index ----------------
__global__ void __launch_bounds__(256)
idx_k(const int* __restrict__ cum, int* __restrict__ idx)
{
    int b = blockIdx.y;
    int t = blockIdx.x * 256 + threadIdx.x;
    const int* c = cum + b * Sv;
    int total = c[Sv - 1];
    int lo = 0, hi = Sv;
    while (lo < hi) { int mid = (lo + hi) >> 1; if (c[mid] <= t) lo = mid + 1; else hi = mid; }
    int ix = lo > (Sv - 1) ? (Sv - 1) : lo;
    idx[b * Tv + t] = (t < total) ? ix : -1;
}

// ---------------- mel for invalid frames ----------------
__global__ void __launch_bounds__(256)
melinv_k(const float* __restrict__ b1, const float* __restrict__ W2,
         const float* __restrict__ b2, float* __restrict__ inv)
{
    __shared__ float sbuf[8];
    int nm = blockIdx.x, tid = threadIdx.x;
    float v = 0.f;
    for (int f = tid; f < FFv; f += 256) {
        float r = b1[f]; r = r > 0.f ? r : 0.f;
        v += r * W2[(size_t)f * NMv + nm];
    }
    v = blk_sum(v, sbuf);
    if (tid == 0) inv[nm] = v + b2[nm];
}

// ---------------- gather mel rows into [B, NM, T] ----------------
__global__ void __launch_bounds__(256)
gather_k(const int* __restrict__ idx, const float* __restrict__ mels,
         const float* __restrict__ inv, float* __restrict__ mel)
{
    int t = blockIdx.x * 256 + threadIdx.x;
    int bn = blockIdx.y;
    int b = bn / NMv, nm = bn % NMv;
    int iv = idx[b * Tv + t];
    mel[(size_t)bn * Tv + t] =
        (iv < 0) ? inv[nm] : mels[((size_t)b * Sv + iv) * NMv + nm];
}

// ---------------- host launcher ----------------
static inline int gsmem(int nt) { return 2 * (2 * 128 * 80 + 2 * nt * 80); }

extern "C" void kernel_launch(void* const* d_in, const int* in_sizes, int n_in,
                              void* d_out, int out_size)
{
    const int*   ids    = (const int*)  d_in[0];
    const int*   lens   = (const int*)  d_in[1];
    const float* emb    = (const float*)d_in[3];
    const float* pe     = (const float*)d_in[4];
    const float* Wqkv   = (const float*)d_in[5];
    const float* bqkv   = (const float*)d_in[6];
    const float* Wo     = (const float*)d_in[7];
    const float* bo     = (const float*)d_in[8];
    const float* ln1s   = (const float*)d_in[9];
    const float* ln1b   = (const float*)d_in[10];
    const float* ln2s   = (const float*)d_in[11];
    const float* ln2b   = (const float*)d_in[12];
    const float* W1     = (const float*)d_in[13];
    const float* b1     = (const float*)d_in[14];
    const float* W2     = (const float*)d_in[15];
    const float* b2     = (const float*)d_in[16];
    const float* melW1  = (const float*)d_in[17];
    const float* melb1  = (const float*)d_in[18];
    const float* melW2  = (const float*)d_in[19];
    const float* melb2  = (const float*)d_in[20];
    const float* durW1  = (const float*)d_in[21];
    const float* durb1  = (const float*)d_in[22];
    const float* durW2  = (const float*)d_in[23];
    const float* durb2  = (const float*)d_in[24];

    float* out     = (float*)d_out;
    float* out_mel = out;
    float* out_dur = out + (size_t)Bv * NMv * Tv;
    float* out_enc = out_dur + (size_t)Bv * Sv;

    float *x, *qkv, *attn, *tmp, *big, *durh, *mels, *inv;
    int *cum, *idxp;
    __nv_bfloat16 *qkvTH, *qkvTL, *WoTH, *WoTL, *W1TH, *W1TL, *W2TH, *W2TL;
    __nv_bfloat16 *m1TH, *m1TL, *m2TH, *m2TL, *d1TH, *d1TL;
    cudaGetSymbolAddress((void**)&x,     g_x);
    cudaGetSymbolAddress((void**)&qkv,   g_qkv);
    cudaGetSymbolAddress((void**)&attn,  g_attn);
    cudaGetSymbolAddress((void**)&tmp,   g_tmp);
    cudaGetSymbolAddress((void**)&big,   g_big);
    cudaGetSymbolAddress((void**)&durh,  g_durh);
    cudaGetSymbolAddress((void**)&mels,  g_mels);
    cudaGetSymbolAddress((void**)&inv,   g_inv);
    cudaGetSymbolAddress((void**)&cum,   g_cum);
    cudaGetSymbolAddress((void**)&idxp,  g_idx);
    cudaGetSymbolAddress((void**)&qkvTH, g_qkvTH);
    cudaGetSymbolAddress((void**)&qkvTL, g_qkvTL);
    cudaGetSymbolAddress((void**)&WoTH,  g_WoTH);
    cudaGetSymbolAddress((void**)&WoTL,  g_WoTL);
    cudaGetSymbolAddress((void**)&W1TH,  g_W1TH);
    cudaGetSymbolAddress((void**)&W1TL,  g_W1TL);
    cudaGetSymbolAddress((void**)&W2TH,  g_W2TH);
    cudaGetSymbolAddress((void**)&W2TL,  g_W2TL);
    cudaGetSymbolAddress((void**)&m1TH,  g_m1TH);
    cudaGetSymbolAddress((void**)&m1TL,  g_m1TL);
    cudaGetSymbolAddress((void**)&m2TH,  g_m2TH);
    cudaGetSymbolAddress((void**)&m2TL,  g_m2TL);
    cudaGetSymbolAddress((void**)&d1TH,  g_d1TH);
    cudaGetSymbolAddress((void**)&d1TL,  g_d1TL);

    const int attn_smem = 2 * Sv * DHv * (int)sizeof(float);
    cudaFuncSetAttribute(attn_k, cudaFuncAttributeMaxDynamicSharedMemorySize, attn_smem);
    const int sm64 = gsmem(64), sm128 = gsmem(128);
    cudaFuncSetAttribute(mgemm_k<64,1>,  cudaFuncAttributeMaxDynamicSharedMemorySize, sm64);
    cudaFuncSetAttribute(mgemm_k<64,2>,  cudaFuncAttributeMaxDynamicSharedMemorySize, sm64);
    cudaFuncSetAttribute(mgemm_k<128,2>, cudaFuncAttributeMaxDynamicSharedMemorySize, sm128);

    dim3 tb(32, 8);
    tsplit_k<<<dim3(48, 16, Lv), tb>>>(Wqkv,  qkvTH, qkvTL, Dv, 3 * Dv);
    tsplit_k<<<dim3(16, 16, Lv), tb>>>(Wo,    WoTH,  WoTL,  Dv, Dv);
    tsplit_k<<<dim3(64, 16, Lv), tb>>>(W1,    W1TH,  W1TL,  Dv, FFv);
    tsplit_k<<<dim3(16, 64, Lv), tb>>>(W2,    W2TH,  W2TL,  FFv, Dv);
    tsplit_k<<<dim3(64, 16, 1),  tb>>>(melW1, m1TH,  m1TL,  Dv, FFv);
    tsplit_k<<<dim3(3,  64, 1),  tb>>>(melW2, m2TH,  m2TL,  FFv, NMv);
    tsplit_k<<<dim3(8,  16, 1),  tb>>>(durW1, d1TH,  d1TL,  Dv, 256);

    embed_k<<<NTOK, 128>>>(ids, emb, pe, x);

    for (int l = 0; l < Lv; l++) {
        mgemm_k<64,1><<<dim3(24, 32), 256, sm64>>>(
            x, qkvTH + (size_t)l * 3 * Dv * Dv, qkvTL + (size_t)l * 3 * Dv * Dv,
            bqkv + l * 3 * Dv, qkv, NTOK, 3 * Dv, Dv);
        attn_k<<<dim3(Hv, Bv), 256, attn_smem>>>(qkv, lens, attn);
        mgemm_k<64,1><<<dim3(8, 32), 256, sm64>>>(
            attn, WoTH + (size_t)l * Dv * Dv, WoTL + (size_t)l * Dv * Dv,
            bo + l * Dv, tmp, NTOK, Dv, Dv);
        add_ln_k<<<NTOK, 128>>>(x, tmp, ln1s + l * Dv, ln1b + l * Dv, x);
        mgemm_k<128,2><<<dim3(16, 32), 256, sm128>>>(
            x, W1TH + (size_t)l * FFv * Dv, W1TL + (size_t)l * FFv * Dv,
            b1 + l * FFv, big, NTOK, FFv, Dv);
        mgemm_k<64,1><<<dim3(8, 32), 256, sm64>>>(
            big, W2TH + (size_t)l * Dv * FFv, W2TL + (size_t)l * Dv * FFv,
            b2 + l * Dv, tmp, NTOK, Dv, FFv);
        add_ln_k<<<NTOK, 128>>>(x, tmp, ln2s + l * Dv, ln2b + l * Dv, x);
    }

    cudaMemcpyAsync(out_enc, x, (size_t)NTOK * Dv * sizeof(float),
                    cudaMemcpyDeviceToDevice);

    // duration head
    mgemm_k<64,2><<<dim3(4, 32), 256, sm64>>>(x, d1TH, d1TL, durb1, durh,
                                              NTOK, 256, Dv);
    dur_head_k<<<NTOK, 256>>>(durh, durW2, durb2, out_dur);
    cumsum_k<<<Bv, 256>>>(out_dur, cum);

    // mel head on source tokens (gather commutes with row-wise MLP)
    mgemm_k<128,2><<<dim3(16, 32), 256, sm128>>>(x, m1TH, m1TL, melb1, big,
                                                 NTOK, FFv, Dv);
    mgemm_k<64,1><<<dim3(2, 32), 256, sm64>>>(big, m2TH, m2TL, melb2, mels,
                                              NTOK, NMv, FFv);
    melinv_k<<<NMv, 256>>>(melb1, melW2, melb2, inv);

    idx_k<<<dim3(Tv / 256, Bv), 256>>>(cum, idxp);
    gather_k<<<dim3(Tv / 256, Bv * NMv), 256>>>(idxp, mels, inv, out_mel);
}

// round 7
// speedup vs baseline: 1.6411x; 1.2314x over previous
#include <cuda_runtime.h>
#include <cuda_fp16.h>
#include <math.h>
#include <stdint.h>

// ---------------- problem constants ----------------
#define Bv   16
#define Sv   256
#define Tv   2048
#define Dv   512
#define Hv   8
#define DHv  64
#define Lv   6
#define FFv  2048
#define NMv  80
#define NTOK (Bv*Sv)            // 4096 tokens

// ---------------- scratch (no allocs allowed) ----------------
__device__ float g_x   [NTOK*Dv];
__device__ float g_qkv [NTOK*3*Dv];
__device__ float g_attn[NTOK*Dv];
__device__ float g_tmp [NTOK*Dv];
__device__ float g_big [NTOK*FFv];
__device__ float g_durh[NTOK*256];
__device__ float g_mels[NTOK*NMv];
__device__ float g_inv [NMv];
__device__ int   g_cum [Bv*Sv];
__device__ int   g_idx [Bv*Tv];
// transposed weights ([N,K] K-major, single fp16)
__device__ __half g_qkvT[Lv*3*Dv*Dv];
__device__ __half g_WoT [Lv*Dv*Dv];
__device__ __half g_W1T [Lv*FFv*Dv];
__device__ __half g_W2T [Lv*Dv*FFv];
__device__ __half g_m1T [FFv*Dv];
__device__ __half g_m2T [NMv*FFv];
__device__ __half g_d1T [256*Dv];

// ---------------- low-level helpers ----------------
__device__ __forceinline__ uint32_t smem_u32(const void* p) {
    uint32_t a;
    asm("{ .reg .u64 t; cvta.to.shared.u64 t, %1; cvt.u32.u64 %0, t; }" : "=r"(a) : "l"(p));
    return a;
}
__device__ __forceinline__ void ldsm4(uint32_t& a0, uint32_t& a1, uint32_t& a2,
                                      uint32_t& a3, uint32_t addr) {
    asm volatile("ldmatrix.sync.aligned.m8n8.x4.shared.b16 {%0,%1,%2,%3}, [%4];"
                 : "=r"(a0), "=r"(a1), "=r"(a2), "=r"(a3) : "r"(addr));
}
__device__ __forceinline__ void ldsm2(uint32_t& b0, uint32_t& b1, uint32_t addr) {
    asm volatile("ldmatrix.sync.aligned.m8n8.x2.shared.b16 {%0,%1}, [%2];"
                 : "=r"(b0), "=r"(b1) : "r"(addr));
}
__device__ __forceinline__ void mma_f16(float* c, const uint32_t* a,
                                        uint32_t b0, uint32_t b1) {
    asm volatile("mma.sync.aligned.m16n8k16.row.col.f32.f16.f16.f32 "
                 "{%0,%1,%2,%3}, {%4,%5,%6,%7}, {%8,%9}, {%0,%1,%2,%3};"
                 : "+f"(c[0]), "+f"(c[1]), "+f"(c[2]), "+f"(c[3])
                 : "r"(a[0]), "r"(a[1]), "r"(a[2]), "r"(a[3]), "r"(b0), "r"(b1));
}
// split two fp32 into packed fp16x2 hi + fp16x2 lo
__device__ __forceinline__ void split2h(float x, float y, uint32_t& hi, uint32_t& lo) {
    __half2 h = __floats2half2_rn(x, y);
    float hx = __low2float(h);
    float hy = __high2float(h);
    __half2 l2 = __floats2half2_rn(x - hx, y - hy);
    hi = *(uint32_t*)&h;
    lo = *(uint32_t*)&l2;
}

// ================= split-fp16 mma.sync GEMM (2-term) ============================
// C[M,N] = (Ah+Al)[M,K] @ Bt[N,K]^T (+bias)(+relu)
// A fp32 in gmem, split to fp16 hi/lo in-kernel. B pre-rounded fp16.
// Block 128 x NT_ x 32, 8 warps. Warp tile 32 x (NT_/2). M%128==0, K%32==0.
#define RSB     80u                      // smem row stride bytes (64B data + 16B pad)
#define TILE_A  (128u*RSB)               // 10240 B

template<int NT_, int EPI>   // NT_ in {64,128}; EPI: 0 none, 1 bias, 2 bias+relu
__global__ void __launch_bounds__(256, 1)
mgemm_k(const float* __restrict__ A,
        const __half* __restrict__ Bt,
        const float* __restrict__ bias, float* __restrict__ C,
        int M, int N, int K)
{
    constexpr uint32_t TILE_BN = (uint32_t)NT_ * RSB;
    constexpr uint32_t STAGE = 2u * TILE_A + TILE_BN;   // A_hi, A_lo, B
    constexpr int NI = NT_ / 16;                 // B ni count per warp
    extern __shared__ char smem[];
    uint32_t sb = smem_u32(smem);
    int tid = threadIdx.x, wid = tid >> 5, l = tid & 31;
    int m0 = blockIdx.y * 128, n0 = blockIdx.x * NT_;
    int wm = (wid & 3) * 32, wn = (wid >> 2) * (NT_ / 2);

    float acc[2][NI][4];
    #pragma unroll
    for (int mi = 0; mi < 2; mi++)
        #pragma unroll
        for (int ni = 0; ni < NI; ni++)
            #pragma unroll
            for (int q = 0; q < 4; q++) acc[mi][ni][q] = 0.f;

    int ar_ = tid >> 3, ac_ = tid & 7;    // A tile coords (32 rows x 8 col-groups)
    int br_ = tid >> 2, bc_ = tid & 3;    // B tile coords (64 rows x 4 col-groups)

    float4 ard[4];
    uint4  brd[NT_/64];

    const int NT = K / 32;

    // ---- prefetch tile 0 ----
    {
        #pragma unroll
        for (int i = 0; i < 4; i++)
            ard[i] = *(const float4*)(A + (size_t)(m0 + ar_ + i * 32) * K + ac_ * 4);
        #pragma unroll
        for (int i = 0; i < NT_/64; i++) {
            int r = br_ + i * 64;
            if (n0 + r < N)
                brd[i] = *(const uint4*)(Bt + (size_t)(n0 + r) * K + bc_ * 8);
            else
                brd[i] = make_uint4(0,0,0,0);
        }
    }
    // ---- store tile 0 ----
    {
        #pragma unroll
        for (int i = 0; i < 4; i++) {
            uint32_t h0, h1, l0, l1;
            split2h(ard[i].x, ard[i].y, h0, l0);
            split2h(ard[i].z, ard[i].w, h1, l1);
            uint32_t off = (uint32_t)(ar_ + i * 32) * RSB + ac_ * 8u;
            *(uint2*)(smem + off)          = make_uint2(h0, h1);
            *(uint2*)(smem + TILE_A + off) = make_uint2(l0, l1);
        }
        #pragma unroll
        for (int i = 0; i < NT_/64; i++) {
            uint32_t off = (uint32_t)(br_ + i * 64) * RSB + bc_ * 16u;
            *(uint4*)(smem + 2 * TILE_A + off) = brd[i];
        }
    }
    __syncthreads();

    uint32_t aoff = (uint32_t)(wm + (l & 15)) * RSB + (uint32_t)(l >> 4) * 16u;
    uint32_t boff = (uint32_t)(wn + (l & 7)) * RSB + (uint32_t)((l >> 3) & 1) * 16u;

    for (int kt = 0; kt < NT; kt++) {
        int s = kt & 1;
        // prefetch next tile into registers
        if (kt + 1 < NT) {
            int k0 = (kt + 1) * 32;
            #pragma unroll
            for (int i = 0; i < 4; i++)
                ard[i] = *(const float4*)(A + (size_t)(m0 + ar_ + i * 32) * K + k0 + ac_ * 4);
            #pragma unroll
            for (int i = 0; i < NT_/64; i++) {
                int r = br_ + i * 64;
                if (n0 + r < N)
                    brd[i] = *(const uint4*)(Bt + (size_t)(n0 + r) * K + k0 + bc_ * 8);
                else
                    brd[i] = make_uint4(0,0,0,0);
            }
        }
        // compute on stage s
        {
            uint32_t aH_ = sb + (uint32_t)s * STAGE;
            uint32_t aL_ = aH_ + TILE_A;
            uint32_t bB_ = aH_ + 2 * TILE_A;
            #pragma unroll
            for (int ks = 0; ks < 2; ks++) {
                uint32_t ah[2][4], al[2][4];
                #pragma unroll
                for (int mi = 0; mi < 2; mi++) {
                    uint32_t ad = aoff + (uint32_t)mi * 16u * RSB + (uint32_t)ks * 32u;
                    ldsm4(ah[mi][0], ah[mi][1], ah[mi][2], ah[mi][3], aH_ + ad);
                    ldsm4(al[mi][0], al[mi][1], al[mi][2], al[mi][3], aL_ + ad);
                }
                #pragma unroll
                for (int ni = 0; ni < NI; ni++) {
                    uint32_t bd = boff + (uint32_t)ni * 8u * RSB + (uint32_t)ks * 32u;
                    uint32_t b0, b1;
                    ldsm2(b0, b1, bB_ + bd);
                    #pragma unroll
                    for (int mi = 0; mi < 2; mi++) {
                        mma_f16(acc[mi][ni], ah[mi], b0, b1);
                        mma_f16(acc[mi][ni], al[mi], b0, b1);
                    }
                }
            }
        }
        __syncthreads();
        if (kt + 1 < NT) {
            int sn = (kt + 1) & 1;
            char* dst = smem + (uint32_t)sn * STAGE;
            #pragma unroll
            for (int i = 0; i < 4; i++) {
                uint32_t h0, h1, l0, l1;
                split2h(ard[i].x, ard[i].y, h0, l0);
                split2h(ard[i].z, ard[i].w, h1, l1);
                uint32_t off = (uint32_t)(ar_ + i * 32) * RSB + ac_ * 8u;
                *(uint2*)(dst + off)          = make_uint2(h0, h1);
                *(uint2*)(dst + TILE_A + off) = make_uint2(l0, l1);
            }
            #pragma unroll
            for (int i = 0; i < NT_/64; i++) {
                uint32_t off = (uint32_t)(br_ + i * 64) * RSB + bc_ * 16u;
                *(uint4*)(dst + 2 * TILE_A + off) = brd[i];
            }
            __syncthreads();
        }
    }

    // epilogue
    int r_lo = l >> 2, cpair = (l & 3) * 2;
    #pragma unroll
    for (int mi = 0; mi < 2; mi++) {
        int gr0 = m0 + wm + mi * 16 + r_lo;
        #pragma unroll
        for (int ni = 0; ni < NI; ni++) {
            int gc = n0 + wn + ni * 8 + cpair;
            if (gc < N) {
                float b0 = 0.f, b1 = 0.f;
                if (EPI >= 1) { b0 = bias[gc]; b1 = bias[gc + 1]; }
                float v0 = acc[mi][ni][0] + b0, v1 = acc[mi][ni][1] + b1;
                float v2 = acc[mi][ni][2] + b0, v3 = acc[mi][ni][3] + b1;
                if (EPI == 2) {
                    v0 = fmaxf(v0, 0.f); v1 = fmaxf(v1, 0.f);
                    v2 = fmaxf(v2, 0.f); v3 = fmaxf(v3, 0.f);
                }
                *(float2*)(C + (size_t)gr0 * N + gc)       = make_float2(v0, v1);
                *(float2*)(C + (size_t)(gr0 + 8) * N + gc) = make_float2(v2, v3);
            }
        }
    }
}

// ---------------- transpose + fp16 round: in[z][R][C] fp32 -> out[z][C][R] fp16 --
__global__ void __launch_bounds__(256)
tsplit_k(const float* __restrict__ in, __half* __restrict__ outH, int R, int C)
{
    __shared__ float t[32][33];
    size_t zo = (size_t)blockIdx.z * R * C;
    int c0 = blockIdx.x * 32, r0 = blockIdx.y * 32;
    int x = threadIdx.x, y = threadIdx.y;
    #pragma unroll
    for (int i = 0; i < 32; i += 8) {
        int r = r0 + y + i, c = c0 + x;
        if (r < R && c < C) t[y + i][x] = in[zo + (size_t)r * C + c];
    }
    __syncthreads();
    #pragma unroll
    for (int i = 0; i < 32; i += 8) {
        int c = c0 + y + i, r = r0 + x;
        if (c < C && r < R)
            outH[zo + (size_t)c * R + r] = __float2half_rn(t[x][y + i]);
    }
}

// ---------------- misc helpers ----------------
__device__ __forceinline__ float blk_sum(float v, float* sbuf) {
    __syncthreads();
    int lane = threadIdx.x & 31, w = threadIdx.x >> 5;
    #pragma unroll
    for (int o = 16; o; o >>= 1) v += __shfl_xor_sync(0xffffffffu, v, o);
    if (lane == 0) sbuf[w] = v;
    __syncthreads();
    int nw = blockDim.x >> 5;
    float r = (threadIdx.x < nw) ? sbuf[threadIdx.x] : 0.f;
    if (w == 0) {
        #pragma unroll
        for (int o = 16; o; o >>= 1) r += __shfl_xor_sync(0xffffffffu, r, o);
        if (lane == 0) sbuf[0] = r;
    }
    __syncthreads();
    return sbuf[0];
}

// ---------------- embedding + positional encoding ----------------
__global__ void __launch_bounds__(128)
embed_k(const int* __restrict__ ids, const float* __restrict__ emb,
        const float* __restrict__ pe, float* __restrict__ x)
{
    int token = blockIdx.x;
    int tid = threadIdx.x;
    int s = token % Sv;
    int id = ids[token];
    float4 e = ((const float4*)(emb + (size_t)id * Dv))[tid];
    float4 p = ((const float4*)(pe + (size_t)s * Dv))[tid];
    e.x += p.x; e.y += p.y; e.z += p.z; e.w += p.w;
    ((float4*)(x + (size_t)token * Dv))[tid] = e;
}

// ---------------- fused attention (one block per (b,h), online softmax) ------
__global__ void __launch_bounds__(256)
attn_k(const float* __restrict__ qkv, const int* __restrict__ lens,
       float* __restrict__ o)
{
    extern __shared__ float sh[];
    float* Ks = sh;
    float* Vs = sh + Sv * DHv;
    int h = blockIdx.x, b = blockIdx.y;
    int t = threadIdx.x;

    const float* base = qkv + (size_t)b * Sv * (3 * Dv);
    const float4* krow = (const float4*)(base + (size_t)t * 3 * Dv + Dv     + h * DHv);
    const float4* vrow = (const float4*)(base + (size_t)t * 3 * Dv + 2 * Dv + h * DHv);
    float4* ksd = (float4*)(Ks + t * DHv);
    float4* vsd = (float4*)(Vs + t * DHv);
    #pragma unroll
    for (int i = 0; i < 16; i++) { ksd[i] = krow[i]; vsd[i] = vrow[i]; }
    __syncthreads();

    int len = lens[b];
    float4 q4[16];
    const float4* qrow = (const float4*)(base + (size_t)t * 3 * Dv + h * DHv);
    #pragma unroll
    for (int i = 0; i < 16; i++) q4[i] = qrow[i];

    float4 a4[16];
    #pragma unroll
    for (int i = 0; i < 16; i++) a4[i] = make_float4(0.f, 0.f, 0.f, 0.f);

    const float scale = 0.125f;
    float m = -1e30f, l = 0.f;

    for (int j = 0; j < len; j++) {
        const float4* kj = (const float4*)(Ks + j * DHv);
        float s = 0.f;
        #pragma unroll
        for (int i = 0; i < 16; i++) {
            float4 kv = kj[i];
            s += q4[i].x * kv.x + q4[i].y * kv.y + q4[i].z * kv.z + q4[i].w * kv.w;
        }
        s *= scale;
        if (s > m) {
            float corr = __expf(m - s);
            l *= corr;
            #pragma unroll
            for (int i = 0; i < 16; i++) {
                a4[i].x *= corr; a4[i].y *= corr; a4[i].z *= corr; a4[i].w *= corr;
            }
            m = s;
        }
        float e = __expf(s - m);
        l += e;
        const float4* vj = (const float4*)(Vs + j * DHv);
        #pragma unroll
        for (int i = 0; i < 16; i++) {
            float4 vv = vj[i];
            a4[i].x += e * vv.x; a4[i].y += e * vv.y;
            a4[i].z += e * vv.z; a4[i].w += e * vv.w;
        }
    }

    float inv = (l > 0.f) ? 1.f / l : 0.f;
    float4* orow = (float4*)(o + ((size_t)b * Sv + t) * Dv + h * DHv);
    #pragma unroll
    for (int i = 0; i < 16; i++) {
        float4 r = a4[i];
        r.x *= inv; r.y *= inv; r.z *= inv; r.w *= inv;
        orow[i] = r;
    }
}

// ---------------- residual add + LayerNorm ----------------
__global__ void __launch_bounds__(128)
add_ln_k(const float* __restrict__ x, const float* __restrict__ y,
         const float* __restrict__ s, const float* __restrict__ bta,
         float* __restrict__ out)
{
    __shared__ float sbuf[8];
    int row = blockIdx.x, tid = threadIdx.x;
    float4 v = ((const float4*)(x + (size_t)row * Dv))[tid];
    float4 w = ((const float4*)(y + (size_t)row * Dv))[tid];
    v.x += w.x; v.y += w.y; v.z += w.z; v.w += w.w;

    float sum = blk_sum(v.x + v.y + v.z + v.w, sbuf);
    float mean = sum * (1.f / Dv);
    float dx = v.x - mean, dy = v.y - mean, dz = v.z - mean, dw = v.w - mean;
    float var = blk_sum(dx*dx + dy*dy + dz*dz + dw*dw, sbuf) * (1.f / Dv);
    float rstd = rsqrtf(var + 1e-5f);

    float4 sv = ((const float4*)s)[tid];
    float4 bv = ((const float4*)bta)[tid];
    float4 r;
    r.x = dx * rstd * sv.x + bv.x;
    r.y = dy * rstd * sv.y + bv.y;
    r.z = dz * rstd * sv.z + bv.z;
    r.w = dw * rstd * sv.w + bv.w;
    ((float4*)(out + (size_t)row * Dv))[tid] = r;
}

// ---------------- duration head ----------------
__global__ void __launch_bounds__(256)
dur_head_k(const float* __restrict__ durh, const float* __restrict__ W2,
           const float* __restrict__ b2, float* __restrict__ dur)
{
    __shared__ float sbuf[8];
    int row = blockIdx.x, tid = threadIdx.x;
    float v = durh[(size_t)row * 256 + tid] * W2[tid];
    v = blk_sum(v, sbuf);
    if (tid == 0) {
        float z = v + b2[0];
        dur[row] = (z > 20.f) ? z : log1pf(expf(z));
    }
}

// ---------------- parallel cumulative durations ----------------
__global__ void __launch_bounds__(256)
cumsum_k(const float* __restrict__ dur, int* __restrict__ cum)
{
    __shared__ int ws[8];
    int b = blockIdx.x, t = threadIdx.x;
    int lane = t & 31, w = t >> 5;
    int d = (int)rintf(dur[b * Sv + t]);
    if (d < 1) d = 1;
    int v = d;
    #pragma unroll
    for (int o = 1; o < 32; o <<= 1) {
        int u = __shfl_up_sync(0xffffffffu, v, o);
        if (lane >= o) v += u;
    }
    if (lane == 31) ws[w] = v;
    __syncthreads();
    if (t < 8) {
        int s = ws[t];
        #pragma unroll
        for (int o = 1; o < 8; o <<= 1) {
            int u = __shfl_up_sync(0x000000ffu, s, o);
            if (t >= o) s += u;
        }
        ws[t] = s;
    }
    __syncthreads();
    int off = (w > 0) ? ws[w - 1] : 0;
    cum[b * Sv + t] = v + off;
}

// ---------------- frame -> source index ----------------
__global__ void __launch_bounds__(256)
idx_k(const int* __restrict__ cum, int* __restrict__ idx)
{
    int b = blockIdx.y;
    int t = blockIdx.x * 256 + threadIdx.x;
    const int* c = cum + b * Sv;
    int total = c[Sv - 1];
    int lo = 0, hi = Sv;
    while (lo < hi) { int mid = (lo + hi) >> 1; if (c[mid] <= t) lo = mid + 1; else hi = mid; }
    int ix = lo > (Sv - 1) ? (Sv - 1) : lo;
    idx[b * Tv + t] = (t < total) ? ix : -1;
}

// ---------------- mel for invalid frames ----------------
__global__ void __launch_bounds__(256)
melinv_k(const float* __restrict__ b1, const float* __restrict__ W2,
         const float* __restrict__ b2, float* __restrict__ inv)
{
    __shared__ float sbuf[8];
    int nm = blockIdx.x, tid = threadIdx.x;
    float v = 0.f;
    for (int f = tid; f < FFv; f += 256) {
        float r = b1[f]; r = r > 0.f ? r : 0.f;
        v += r * W2[(size_t)f * NMv + nm];
    }
    v = blk_sum(v, sbuf);
    if (tid == 0) inv[nm] = v + b2[nm];
}

// ---------------- gather mel rows into [B, NM, T] ----------------
__global__ void __launch_bounds__(256)
gather_k(const int* __restrict__ idx, const float* __restrict__ mels,
         const float* __restrict__ inv, float* __restrict__ mel)
{
    int t = blockIdx.x * 256 + threadIdx.x;
    int bn = blockIdx.y;
    int b = bn / NMv, nm = bn % NMv;
    int iv = idx[b * Tv + t];
    mel[(size_t)bn * Tv + t] =
        (iv < 0) ? inv[nm] : mels[((size_t)b * Sv + iv) * NMv + nm];
}

// ---------------- host launcher ----------------
static inline int gsmem(int nt) { return 2 * (2 * 128 * 80 + nt * 80); }

extern "C" void kernel_launch(void* const* d_in, const int* in_sizes, int n_in,
                              void* d_out, int out_size)
{
    const int*   ids    = (const int*)  d_in[0];
    const int*   lens   = (const int*)  d_in[1];
    const float* emb    = (const float*)d_in[3];
    const float* pe     = (const float*)d_in[4];
    const float* Wqkv   = (const float*)d_in[5];
    const float* bqkv   = (const float*)d_in[6];
    const float* Wo     = (const float*)d_in[7];
    const float* bo     = (const float*)d_in[8];
    const float* ln1s   = (const float*)d_in[9];
    const float* ln1b   = (const float*)d_in[10];
    const float* ln2s   = (const float*)d_in[11];
    const float* ln2b   = (const float*)d_in[12];
    const float* W1     = (const float*)d_in[13];
    const float* b1     = (const float*)d_in[14];
    const float* W2     = (const float*)d_in[15];
    const float* b2     = (const float*)d_in[16];
    const float* melW1  = (const float*)d_in[17];
    const float* melb1  = (const float*)d_in[18];
    const float* melW2  = (const float*)d_in[19];
    const float* melb2  = (const float*)d_in[20];
    const float* durW1  = (const float*)d_in[21];
    const float* durb1  = (const float*)d_in[22];
    const float* durW2  = (const float*)d_in[23];
    const float* durb2  = (const float*)d_in[24];

    float* out     = (float*)d_out;
    float* out_mel = out;
    float* out_dur = out + (size_t)Bv * NMv * Tv;
    float* out_enc = out_dur + (size_t)Bv * Sv;

    float *x, *qkv, *attn, *tmp, *big, *durh, *mels, *inv;
    int *cum, *idxp;
    __half *qkvT, *WoT, *W1T, *W2T, *m1T, *m2T, *d1T;
    cudaGetSymbolAddress((void**)&x,    g_x);
    cudaGetSymbolAddress((void**)&qkv,  g_qkv);
    cudaGetSymbolAddress((void**)&attn, g_attn);
    cudaGetSymbolAddress((void**)&tmp,  g_tmp);
    cudaGetSymbolAddress((void**)&big,  g_big);
    cudaGetSymbolAddress((void**)&durh, g_durh);
    cudaGetSymbolAddress((void**)&mels, g_mels);
    cudaGetSymbolAddress((void**)&inv,  g_inv);
    cudaGetSymbolAddress((void**)&cum,  g_cum);
    cudaGetSymbolAddress((void**)&idxp, g_idx);
    cudaGetSymbolAddress((void**)&qkvT, g_qkvT);
    cudaGetSymbolAddress((void**)&WoT,  g_WoT);
    cudaGetSymbolAddress((void**)&W1T,  g_W1T);
    cudaGetSymbolAddress((void**)&W2T,  g_W2T);
    cudaGetSymbolAddress((void**)&m1T,  g_m1T);
    cudaGetSymbolAddress((void**)&m2T,  g_m2T);
    cudaGetSymbolAddress((void**)&d1T,  g_d1T);

    const int attn_smem = 2 * Sv * DHv * (int)sizeof(float);
    cudaFuncSetAttribute(attn_k, cudaFuncAttributeMaxDynamicSharedMemorySize, attn_smem);
    const int sm64 = gsmem(64), sm128 = gsmem(128);
    cudaFuncSetAttribute(mgemm_k<64,1>,  cudaFuncAttributeMaxDynamicSharedMemorySize, sm64);
    cudaFuncSetAttribute(mgemm_k<64,2>,  cudaFuncAttributeMaxDynamicSharedMemorySize, sm64);
    cudaFuncSetAttribute(mgemm_k<128,2>, cudaFuncAttributeMaxDynamicSharedMemorySize, sm128);

    dim3 tb(32, 8);
    tsplit_k<<<dim3(48, 16, Lv), tb>>>(Wqkv,  qkvT, Dv, 3 * Dv);
    tsplit_k<<<dim3(16, 16, Lv), tb>>>(Wo,    WoT,  Dv, Dv);
    tsplit_k<<<dim3(64, 16, Lv), tb>>>(W1,    W1T,  Dv, FFv);
    tsplit_k<<<dim3(16, 64, Lv), tb>>>(W2,    W2T,  FFv, Dv);
    tsplit_k<<<dim3(64, 16, 1),  tb>>>(melW1, m1T,  Dv, FFv);
    tsplit_k<<<dim3(3,  64, 1),  tb>>>(melW2, m2T,  FFv, NMv);
    tsplit_k<<<dim3(8,  16, 1),  tb>>>(durW1, d1T,  Dv, 256);

    embed_k<<<NTOK, 128>>>(ids, emb, pe, x);

    for (int l = 0; l < Lv; l++) {
        mgemm_k<64,1><<<dim3(24, 32), 256, sm64>>>(
            x, qkvT + (size_t)l * 3 * Dv * Dv, bqkv + l * 3 * Dv, qkv, NTOK, 3 * Dv, Dv);
        attn_k<<<dim3(Hv, Bv), 256, attn_smem>>>(qkv, lens, attn);
        mgemm_k<64,1><<<dim3(8, 32), 256, sm64>>>(
            attn, WoT + (size_t)l * Dv * Dv, bo + l * Dv, tmp, NTOK, Dv, Dv);
        add_ln_k<<<NTOK, 128>>>(x, tmp, ln1s + l * Dv, ln1b + l * Dv, x);
        mgemm_k<128,2><<<dim3(16, 32), 256, sm128>>>(
            x, W1T + (size_t)l * FFv * Dv, b1 + l * FFv, big, NTOK, FFv, Dv);
        mgemm_k<64,1><<<dim3(8, 32), 256, sm64>>>(
            big, W2T + (size_t)l * Dv * FFv, b2 + l * Dv, tmp, NTOK, Dv, FFv);
        add_ln_k<<<NTOK, 128>>>(x, tmp, ln2s + l * Dv, ln2b + l * Dv, x);
    }

    cudaMemcpyAsync(out_enc, x, (size_t)NTOK * Dv * sizeof(float),
                    cudaMemcpyDeviceToDevice);

    // duration head
    mgemm_k<64,2><<<dim3(4, 32), 256, sm64>>>(x, d1T, durb1, durh, NTOK, 256, Dv);
    dur_head_k<<<NTOK, 256>>>(durh, durW2, durb2, out_dur);
    cumsum_k<<<Bv, 256>>>(out_dur, cum);

    // mel head on source tokens (gather commutes with row-wise MLP)
    mgemm_k<128,2><<<dim3(16, 32), 256, sm128>>>(x, m1T, melb1, big, NTOK, FFv, Dv);
    mgemm_k<64,1><<<dim3(2, 32), 256, sm64>>>(big, m2T, melb2, mels, NTOK, NMv, FFv);
    melinv_k<<<NMv, 256>>>(melb1, melW2, melb2, inv);

    idx_k<<<dim3(Tv / 256, Bv), 256>>>(cum, idxp);
    gather_k<<<dim3(Tv / 256, Bv * NMv), 256>>>(idxp, mels, inv, out_mel);
}

// round 8
// speedup vs baseline: 2.0517x; 1.2502x over previous
#include <cuda_runtime.h>
#include <cuda_fp16.h>
#include <math.h>
#include <stdint.h>

// ---------------- problem constants ----------------
#define Bv   16
#define Sv   256
#define Tv   2048
#define Dv   512
#define Hv   8
#define DHv  64
#define Lv   6
#define FFv  2048
#define NMv  80
#define NTOK (Bv*Sv)            // 4096 tokens

// ---------------- scratch (no allocs allowed) ----------------
__device__ float g_x   [NTOK*Dv];
__device__ float g_qkv [NTOK*3*Dv];
__device__ float g_attn[NTOK*Dv];
__device__ float g_tmp [NTOK*Dv];
__device__ float g_big [NTOK*FFv];
__device__ float g_durh[NTOK*256];
__device__ float g_mels[NTOK*NMv];
__device__ float g_inv [NMv];
__device__ int   g_cum [Bv*Sv];
__device__ int   g_idx [Bv*Tv];
// transposed weights ([N,K] K-major, single fp16)
__device__ __half g_qkvT[Lv*3*Dv*Dv];
__device__ __half g_WoT [Lv*Dv*Dv];
__device__ __half g_W1T [Lv*FFv*Dv];
__device__ __half g_W2T [Lv*Dv*FFv];
__device__ __half g_m1T [FFv*Dv];
__device__ __half g_m2T [NMv*FFv];
__device__ __half g_d1T [256*Dv];

// ---------------- low-level helpers ----------------
__device__ __forceinline__ uint32_t smem_u32(const void* p) {
    uint32_t a;
    asm("{ .reg .u64 t; cvta.to.shared.u64 t, %1; cvt.u32.u64 %0, t; }" : "=r"(a) : "l"(p));
    return a;
}
__device__ __forceinline__ void ldsm4(uint32_t& a0, uint32_t& a1, uint32_t& a2,
                                      uint32_t& a3, uint32_t addr) {
    asm volatile("ldmatrix.sync.aligned.m8n8.x4.shared.b16 {%0,%1,%2,%3}, [%4];"
                 : "=r"(a0), "=r"(a1), "=r"(a2), "=r"(a3) : "r"(addr));
}
__device__ __forceinline__ void ldsm2(uint32_t& b0, uint32_t& b1, uint32_t addr) {
    asm volatile("ldmatrix.sync.aligned.m8n8.x2.shared.b16 {%0,%1}, [%2];"
                 : "=r"(b0), "=r"(b1) : "r"(addr));
}
__device__ __forceinline__ void mma_f16(float* c, const uint32_t* a,
                                        uint32_t b0, uint32_t b1) {
    asm volatile("mma.sync.aligned.m16n8k16.row.col.f32.f16.f16.f32 "
                 "{%0,%1,%2,%3}, {%4,%5,%6,%7}, {%8,%9}, {%0,%1,%2,%3};"
                 : "+f"(c[0]), "+f"(c[1]), "+f"(c[2]), "+f"(c[3])
                 : "r"(a[0]), "r"(a[1]), "r"(a[2]), "r"(a[3]), "r"(b0), "r"(b1));
}
// split two fp32 into packed fp16x2 hi + fp16x2 lo
__device__ __forceinline__ void split2h(float x, float y, uint32_t& hi, uint32_t& lo) {
    __half2 h = __floats2half2_rn(x, y);
    float hx = __low2float(h);
    float hy = __high2float(h);
    __half2 l2 = __floats2half2_rn(x - hx, y - hy);
    hi = *(uint32_t*)&h;
    lo = *(uint32_t*)&l2;
}
__device__ __forceinline__ uint32_t packh2(float x, float y) {
    __half2 h = __floats2half2_rn(x, y);
    return *(uint32_t*)&h;
}

// ================= split-fp16 mma.sync GEMM (2-term) ============================
#define RSB     80u
#define TILE_A  (128u*RSB)

template<int NT_, int EPI>
__global__ void __launch_bounds__(256, 1)
mgemm_k(const float* __restrict__ A,
        const __half* __restrict__ Bt,
        const float* __restrict__ bias, float* __restrict__ C,
        int M, int N, int K)
{
    constexpr uint32_t TILE_BN = (uint32_t)NT_ * RSB;
    constexpr uint32_t STAGE = 2u * TILE_A + TILE_BN;
    constexpr int NI = NT_ / 16;
    extern __shared__ char smem[];
    uint32_t sb = smem_u32(smem);
    int tid = threadIdx.x, wid = tid >> 5, l = tid & 31;
    int m0 = blockIdx.y * 128, n0 = blockIdx.x * NT_;
    int wm = (wid & 3) * 32, wn = (wid >> 2) * (NT_ / 2);

    float acc[2][NI][4];
    #pragma unroll
    for (int mi = 0; mi < 2; mi++)
        #pragma unroll
        for (int ni = 0; ni < NI; ni++)
            #pragma unroll
            for (int q = 0; q < 4; q++) acc[mi][ni][q] = 0.f;

    int ar_ = tid >> 3, ac_ = tid & 7;
    int br_ = tid >> 2, bc_ = tid & 3;

    float4 ard[4];
    uint4  brd[NT_/64];

    const int NT = K / 32;

    {
        #pragma unroll
        for (int i = 0; i < 4; i++)
            ard[i] = *(const float4*)(A + (size_t)(m0 + ar_ + i * 32) * K + ac_ * 4);
        #pragma unroll
        for (int i = 0; i < NT_/64; i++) {
            int r = br_ + i * 64;
            if (n0 + r < N)
                brd[i] = *(const uint4*)(Bt + (size_t)(n0 + r) * K + bc_ * 8);
            else
                brd[i] = make_uint4(0,0,0,0);
        }
    }
    {
        #pragma unroll
        for (int i = 0; i < 4; i++) {
            uint32_t h0, h1, l0, l1;
            split2h(ard[i].x, ard[i].y, h0, l0);
            split2h(ard[i].z, ard[i].w, h1, l1);
            uint32_t off = (uint32_t)(ar_ + i * 32) * RSB + ac_ * 8u;
            *(uint2*)(smem + off)          = make_uint2(h0, h1);
            *(uint2*)(smem + TILE_A + off) = make_uint2(l0, l1);
        }
        #pragma unroll
        for (int i = 0; i < NT_/64; i++) {
            uint32_t off = (uint32_t)(br_ + i * 64) * RSB + bc_ * 16u;
            *(uint4*)(smem + 2 * TILE_A + off) = brd[i];
        }
    }
    __syncthreads();

    uint32_t aoff = (uint32_t)(wm + (l & 15)) * RSB + (uint32_t)(l >> 4) * 16u;
    uint32_t boff = (uint32_t)(wn + (l & 7)) * RSB + (uint32_t)((l >> 3) & 1) * 16u;

    for (int kt = 0; kt < NT; kt++) {
        int s = kt & 1;
        if (kt + 1 < NT) {
            int k0 = (kt + 1) * 32;
            #pragma unroll
            for (int i = 0; i < 4; i++)
                ard[i] = *(const float4*)(A + (size_t)(m0 + ar_ + i * 32) * K + k0 + ac_ * 4);
            #pragma unroll
            for (int i = 0; i < NT_/64; i++) {
                int r = br_ + i * 64;
                if (n0 + r < N)
                    brd[i] = *(const uint4*)(Bt + (size_t)(n0 + r) * K + k0 + bc_ * 8);
                else
                    brd[i] = make_uint4(0,0,0,0);
            }
        }
        {
            uint32_t aH_ = sb + (uint32_t)s * STAGE;
            uint32_t aL_ = aH_ + TILE_A;
            uint32_t bB_ = aH_ + 2 * TILE_A;
            #pragma unroll
            for (int ks = 0; ks < 2; ks++) {
                uint32_t ah[2][4], al[2][4];
                #pragma unroll
                for (int mi = 0; mi < 2; mi++) {
                    uint32_t ad = aoff + (uint32_t)mi * 16u * RSB + (uint32_t)ks * 32u;
                    ldsm4(ah[mi][0], ah[mi][1], ah[mi][2], ah[mi][3], aH_ + ad);
                    ldsm4(al[mi][0], al[mi][1], al[mi][2], al[mi][3], aL_ + ad);
                }
                #pragma unroll
                for (int ni = 0; ni < NI; ni++) {
                    uint32_t bd = boff + (uint32_t)ni * 8u * RSB + (uint32_t)ks * 32u;
                    uint32_t b0, b1;
                    ldsm2(b0, b1, bB_ + bd);
                    #pragma unroll
                    for (int mi = 0; mi < 2; mi++) {
                        mma_f16(acc[mi][ni], ah[mi], b0, b1);
                        mma_f16(acc[mi][ni], al[mi], b0, b1);
                    }
                }
            }
        }
        __syncthreads();
        if (kt + 1 < NT) {
            int sn = (kt + 1) & 1;
            char* dst = smem + (uint32_t)sn * STAGE;
            #pragma unroll
            for (int i = 0; i < 4; i++) {
                uint32_t h0, h1, l0, l1;
                split2h(ard[i].x, ard[i].y, h0, l0);
                split2h(ard[i].z, ard[i].w, h1, l1);
                uint32_t off = (uint32_t)(ar_ + i * 32) * RSB + ac_ * 8u;
                *(uint2*)(dst + off)          = make_uint2(h0, h1);
                *(uint2*)(dst + TILE_A + off) = make_uint2(l0, l1);
            }
            #pragma unroll
            for (int i = 0; i < NT_/64; i++) {
                uint32_t off = (uint32_t)(br_ + i * 64) * RSB + bc_ * 16u;
                *(uint4*)(dst + 2 * TILE_A + off) = brd[i];
            }
            __syncthreads();
        }
    }

    int r_lo = l >> 2, cpair = (l & 3) * 2;
    #pragma unroll
    for (int mi = 0; mi < 2; mi++) {
        int gr0 = m0 + wm + mi * 16 + r_lo;
        #pragma unroll
        for (int ni = 0; ni < NI; ni++) {
            int gc = n0 + wn + ni * 8 + cpair;
            if (gc < N) {
                float b0 = 0.f, b1 = 0.f;
                if (EPI >= 1) { b0 = bias[gc]; b1 = bias[gc + 1]; }
                float v0 = acc[mi][ni][0] + b0, v1 = acc[mi][ni][1] + b1;
                float v2 = acc[mi][ni][2] + b0, v3 = acc[mi][ni][3] + b1;
                if (EPI == 2) {
                    v0 = fmaxf(v0, 0.f); v1 = fmaxf(v1, 0.f);
                    v2 = fmaxf(v2, 0.f); v3 = fmaxf(v3, 0.f);
                }
                *(float2*)(C + (size_t)gr0 * N + gc)       = make_float2(v0, v1);
                *(float2*)(C + (size_t)(gr0 + 8) * N + gc) = make_float2(v2, v3);
            }
        }
    }
}

// ================= tensor-core flash attention ==================================
// One block per (b,h). 8 warps x 32 queries. Keys in 4 chunks of 64.
// Q (pre-scaled 1/8) and K split fp16 hi/lo (3-term scores); P,V single fp16.
#define QROW 144u                        // 64 fp16 = 128B + 16B pad
#define VROW 528u                        // 256 fp16 = 512B + 16B pad
#define SM_QH 0u
#define SM_QL 36864u
#define SM_KH 73728u
#define SM_KL 110592u
#define SM_VT 147456u
#define SM_ATT (147456 + 64*528)         // 181248 B

__global__ void __launch_bounds__(256, 1)
fattn_k(const float* __restrict__ qkv, const int* __restrict__ lens,
        float* __restrict__ o)
{
    extern __shared__ char smem[];
    uint32_t sb = smem_u32(smem);
    int h = blockIdx.x, b = blockIdx.y;
    int tid = threadIdx.x, wid = tid >> 5, l = tid & 31;
    int len = lens[b];

    // ---- prologue: load Q (scaled+split), K (split), V^T into smem ----
    {
        const float* base = qkv + (size_t)b * Sv * (3 * Dv);
        const float4* qrow = (const float4*)(base + (size_t)tid * 3 * Dv + h * DHv);
        const float4* krow = (const float4*)(base + (size_t)tid * 3 * Dv + Dv + h * DHv);
        const float4* vrow = (const float4*)(base + (size_t)tid * 3 * Dv + 2 * Dv + h * DHv);
        uint32_t qd = sb + (uint32_t)tid * QROW;
        #pragma unroll
        for (int i = 0; i < 16; i++) {
            float4 q = qrow[i];
            q.x *= 0.125f; q.y *= 0.125f; q.z *= 0.125f; q.w *= 0.125f;
            uint32_t h0, h1, l0, l1;
            split2h(q.x, q.y, h0, l0);
            split2h(q.z, q.w, h1, l1);
            *(uint2*)(smem + (qd - sb) + SM_QH + i * 8u) = make_uint2(h0, h1);
            *(uint2*)(smem + (qd - sb) + SM_QL + i * 8u) = make_uint2(l0, l1);
            float4 k = krow[i];
            split2h(k.x, k.y, h0, l0);
            split2h(k.z, k.w, h1, l1);
            *(uint2*)(smem + (qd - sb) + SM_KH + i * 8u) = make_uint2(h0, h1);
            *(uint2*)(smem + (qd - sb) + SM_KL + i * 8u) = make_uint2(l0, l1);
            float4 v = vrow[i];
            __half* vt = (__half*)(smem + SM_VT);
            vt[(4*i+0) * (VROW/2) + tid] = __float2half_rn(v.x);
            vt[(4*i+1) * (VROW/2) + tid] = __float2half_rn(v.y);
            vt[(4*i+2) * (VROW/2) + tid] = __float2half_rn(v.z);
            vt[(4*i+3) * (VROW/2) + tid] = __float2half_rn(v.w);
        }
    }
    __syncthreads();

    int wq = wid * 32;
    float mrow[2][2], lrow[2][2];
    #pragma unroll
    for (int mi = 0; mi < 2; mi++) { mrow[mi][0] = -1e9f; mrow[mi][1] = -1e9f;
                                     lrow[mi][0] = 0.f;   lrow[mi][1] = 0.f; }
    float acc_o[2][8][4];
    #pragma unroll
    for (int mi = 0; mi < 2; mi++)
        #pragma unroll
        for (int ni = 0; ni < 8; ni++)
            #pragma unroll
            for (int q = 0; q < 4; q++) acc_o[mi][ni][q] = 0.f;

    for (int kc = 0; kc < 4; kc++) {
        int kbase = kc * 64;
        if (kbase >= len) break;

        // ---- scores S = Qs @ K^T (3-term split) ----
        float s_[2][8][4];
        #pragma unroll
        for (int mi = 0; mi < 2; mi++)
            #pragma unroll
            for (int ni = 0; ni < 8; ni++)
                #pragma unroll
                for (int q = 0; q < 4; q++) s_[mi][ni][q] = 0.f;

        #pragma unroll
        for (int kst = 0; kst < 4; kst++) {
            uint32_t qh[2][4], ql[2][4];
            #pragma unroll
            for (int mi = 0; mi < 2; mi++) {
                uint32_t ad = (uint32_t)(wq + mi * 16 + (l & 15)) * QROW
                            + (uint32_t)(l >> 4) * 16u + (uint32_t)kst * 32u;
                ldsm4(qh[mi][0], qh[mi][1], qh[mi][2], qh[mi][3], sb + SM_QH + ad);
                ldsm4(ql[mi][0], ql[mi][1], ql[mi][2], ql[mi][3], sb + SM_QL + ad);
            }
            #pragma unroll
            for (int ni = 0; ni < 8; ni++) {
                uint32_t kd = (uint32_t)(kbase + ni * 8 + (l & 7)) * QROW
                            + (uint32_t)((l >> 3) & 1) * 16u + (uint32_t)kst * 32u;
                uint32_t kh0, kh1, kl0, kl1;
                ldsm2(kh0, kh1, sb + SM_KH + kd);
                ldsm2(kl0, kl1, sb + SM_KL + kd);
                #pragma unroll
                for (int mi = 0; mi < 2; mi++) {
                    mma_f16(s_[mi][ni], qh[mi], kh0, kh1);
                    mma_f16(s_[mi][ni], ql[mi], kh0, kh1);
                    mma_f16(s_[mi][ni], qh[mi], kl0, kl1);
                }
            }
        }

        // ---- mask, row max, online softmax ----
        int kcol = kbase + (l & 3) * 2;
        #pragma unroll
        for (int mi = 0; mi < 2; mi++)
            #pragma unroll
            for (int ni = 0; ni < 8; ni++) {
                int k0 = kcol + ni * 8;
                if (k0 >= len)     { s_[mi][ni][0] = -1e9f; s_[mi][ni][2] = -1e9f; }
                if (k0 + 1 >= len) { s_[mi][ni][1] = -1e9f; s_[mi][ni][3] = -1e9f; }
            }

        #pragma unroll
        for (int mi = 0; mi < 2; mi++) {
            float cm0 = -1e9f, cm1 = -1e9f;
            #pragma unroll
            for (int ni = 0; ni < 8; ni++) {
                cm0 = fmaxf(cm0, fmaxf(s_[mi][ni][0], s_[mi][ni][1]));
                cm1 = fmaxf(cm1, fmaxf(s_[mi][ni][2], s_[mi][ni][3]));
            }
            cm0 = fmaxf(cm0, __shfl_xor_sync(0xffffffffu, cm0, 1));
            cm0 = fmaxf(cm0, __shfl_xor_sync(0xffffffffu, cm0, 2));
            cm1 = fmaxf(cm1, __shfl_xor_sync(0xffffffffu, cm1, 1));
            cm1 = fmaxf(cm1, __shfl_xor_sync(0xffffffffu, cm1, 2));
            float nm0 = fmaxf(mrow[mi][0], cm0);
            float nm1 = fmaxf(mrow[mi][1], cm1);
            float c0 = __expf(mrow[mi][0] - nm0);
            float c1 = __expf(mrow[mi][1] - nm1);
            float rs0 = 0.f, rs1 = 0.f;
            #pragma unroll
            for (int ni = 0; ni < 8; ni++) {
                s_[mi][ni][0] = __expf(s_[mi][ni][0] - nm0);
                s_[mi][ni][1] = __expf(s_[mi][ni][1] - nm0);
                s_[mi][ni][2] = __expf(s_[mi][ni][2] - nm1);
                s_[mi][ni][3] = __expf(s_[mi][ni][3] - nm1);
                rs0 += s_[mi][ni][0] + s_[mi][ni][1];
                rs1 += s_[mi][ni][2] + s_[mi][ni][3];
            }
            rs0 += __shfl_xor_sync(0xffffffffu, rs0, 1);
            rs0 += __shfl_xor_sync(0xffffffffu, rs0, 2);
            rs1 += __shfl_xor_sync(0xffffffffu, rs1, 1);
            rs1 += __shfl_xor_sync(0xffffffffu, rs1, 2);
            lrow[mi][0] = lrow[mi][0] * c0 + rs0;
            lrow[mi][1] = lrow[mi][1] * c1 + rs1;
            mrow[mi][0] = nm0; mrow[mi][1] = nm1;
            #pragma unroll
            for (int ni = 0; ni < 8; ni++) {
                acc_o[mi][ni][0] *= c0; acc_o[mi][ni][1] *= c0;
                acc_o[mi][ni][2] *= c1; acc_o[mi][ni][3] *= c1;
            }
        }

        // ---- O += P @ V  (P single fp16 from score regs, V single fp16) ----
        #pragma unroll
        for (int kj = 0; kj < 4; kj++) {
            uint32_t pa[2][4];
            #pragma unroll
            for (int mi = 0; mi < 2; mi++) {
                pa[mi][0] = packh2(s_[mi][2*kj][0],   s_[mi][2*kj][1]);
                pa[mi][1] = packh2(s_[mi][2*kj][2],   s_[mi][2*kj][3]);
                pa[mi][2] = packh2(s_[mi][2*kj+1][0], s_[mi][2*kj+1][1]);
                pa[mi][3] = packh2(s_[mi][2*kj+1][2], s_[mi][2*kj+1][3]);
            }
            #pragma unroll
            for (int ni = 0; ni < 8; ni++) {
                uint32_t vd = (uint32_t)(ni * 8 + (l & 7)) * VROW
                            + (uint32_t)((l >> 3) & 1) * 16u
                            + (uint32_t)kbase * 2u + (uint32_t)kj * 32u;
                uint32_t v0, v1;
                ldsm2(v0, v1, sb + SM_VT + vd);
                #pragma unroll
                for (int mi = 0; mi < 2; mi++)
                    mma_f16(acc_o[mi][ni], pa[mi], v0, v1);
            }
        }
    }

    // ---- epilogue: normalize + store ----
    #pragma unroll
    for (int mi = 0; mi < 2; mi++) {
        float inv0 = (lrow[mi][0] > 0.f) ? 1.f / lrow[mi][0] : 0.f;
        float inv1 = (lrow[mi][1] > 0.f) ? 1.f / lrow[mi][1] : 0.f;
        int ra = wq + mi * 16 + (l >> 2);
        int rb = ra + 8;
        #pragma unroll
        for (int ni = 0; ni < 8; ni++) {
            int col = h * DHv + ni * 8 + (l & 3) * 2;
            *(float2*)(o + ((size_t)b * Sv + ra) * Dv + col) =
                make_float2(acc_o[mi][ni][0] * inv0, acc_o[mi][ni][1] * inv0);
            *(float2*)(o + ((size_t)b * Sv + rb) * Dv + col) =
                make_float2(acc_o[mi][ni][2] * inv1, acc_o[mi][ni][3] * inv1);
        }
    }
}

// ---------------- transpose + fp16 round: in[z][R][C] fp32 -> out[z][C][R] fp16 --
__global__ void __launch_bounds__(256)
tsplit_k(const float* __restrict__ in, __half* __restrict__ outH, int R, int C)
{
    __shared__ float t[32][33];
    size_t zo = (size_t)blockIdx.z * R * C;
    int c0 = blockIdx.x * 32, r0 = blockIdx.y * 32;
    int x = threadIdx.x, y = threadIdx.y;
    #pragma unroll
    for (int i = 0; i < 32; i += 8) {
        int r = r0 + y + i, c = c0 + x;
        if (r < R && c < C) t[y + i][x] = in[zo + (size_t)r * C + c];
    }
    __syncthreads();
    #pragma unroll
    for (int i = 0; i < 32; i += 8) {
        int c = c0 + y + i, r = r0 + x;
        if (c < C && r < R)
            outH[zo + (size_t)c * R + r] = __float2half_rn(t[x][y + i]);
    }
}

// ---------------- misc helpers ----------------
__device__ __forceinline__ float blk_sum(float v, float* sbuf) {
    __syncthreads();
    int lane = threadIdx.x & 31, w = threadIdx.x >> 5;
    #pragma unroll
    for (int o = 16; o; o >>= 1) v += __shfl_xor_sync(0xffffffffu, v, o);
    if (lane == 0) sbuf[w] = v;
    __syncthreads();
    int nw = blockDim.x >> 5;
    float r = (threadIdx.x < nw) ? sbuf[threadIdx.x] : 0.f;
    if (w == 0) {
        #pragma unroll
        for (int o = 16; o; o >>= 1) r += __shfl_xor_sync(0xffffffffu, r, o);
        if (lane == 0) sbuf[0] = r;
    }
    __syncthreads();
    return sbuf[0];
}

// ---------------- embedding + positional encoding ----------------
__global__ void __launch_bounds__(128)
embed_k(const int* __restrict__ ids, const float* __restrict__ emb,
        const float* __restrict__ pe, float* __restrict__ x)
{
    int token = blockIdx.x;
    int tid = threadIdx.x;
    int s = token % Sv;
    int id = ids[token];
    float4 e = ((const float4*)(emb + (size_t)id * Dv))[tid];
    float4 p = ((const float4*)(pe + (size_t)s * Dv))[tid];
    e.x += p.x; e.y += p.y; e.z += p.z; e.w += p.w;
    ((float4*)(x + (size_t)token * Dv))[tid] = e;
}

// ---------------- residual add + LayerNorm ----------------
__global__ void __launch_bounds__(128)
add_ln_k(const float* __restrict__ x, const float* __restrict__ y,
         const float* __restrict__ s, const float* __restrict__ bta,
         float* __restrict__ out)
{
    __shared__ float sbuf[8];
    int row = blockIdx.x, tid = threadIdx.x;
    float4 v = ((const float4*)(x + (size_t)row * Dv))[tid];
    float4 w = ((const float4*)(y + (size_t)row * Dv))[tid];
    v.x += w.x; v.y += w.y; v.z += w.z; v.w += w.w;

    float sum = blk_sum(v.x + v.y + v.z + v.w, sbuf);
    float mean = sum * (1.f / Dv);
    float dx = v.x - mean, dy = v.y - mean, dz = v.z - mean, dw = v.w - mean;
    float var = blk_sum(dx*dx + dy*dy + dz*dz + dw*dw, sbuf) * (1.f / Dv);
    float rstd = rsqrtf(var + 1e-5f);

    float4 sv = ((const float4*)s)[tid];
    float4 bv = ((const float4*)bta)[tid];
    float4 r;
    r.x = dx * rstd * sv.x + bv.x;
    r.y = dy * rstd * sv.y + bv.y;
    r.z = dz * rstd * sv.z + bv.z;
    r.w = dw * rstd * sv.w + bv.w;
    ((float4*)(out + (size_t)row * Dv))[tid] = r;
}

// ---------------- duration head ----------------
__global__ void __launch_bounds__(256)
dur_head_k(const float* __restrict__ durh, const float* __restrict__ W2,
           const float* __restrict__ b2, float* __restrict__ dur)
{
    __shared__ float sbuf[8];
    int row = blockIdx.x, tid = threadIdx.x;
    float v = durh[(size_t)row * 256 + tid] * W2[tid];
    v = blk_sum(v, sbuf);
    if (tid == 0) {
        float z = v + b2[0];
        dur[row] = (z > 20.f) ? z : log1pf(expf(z));
    }
}

// ---------------- parallel cumulative durations ----------------
__global__ void __launch_bounds__(256)
cumsum_k(const float* __restrict__ dur, int* __restrict__ cum)
{
    __shared__ int ws[8];
    int b = blockIdx.x, t = threadIdx.x;
    int lane = t & 31, w = t >> 5;
    int d = (int)rintf(dur[b * Sv + t]);
    if (d < 1) d = 1;
    int v = d;
    #pragma unroll
    for (int o = 1; o < 32; o <<= 1) {
        int u = __shfl_up_sync(0xffffffffu, v, o);
        if (lane >= o) v += u;
    }
    if (lane == 31) ws[w] = v;
    __syncthreads();
    if (t < 8) {
        int s = ws[t];
        #pragma unroll
        for (int o = 1; o < 8; o <<= 1) {
            int u = __shfl_up_sync(0x000000ffu, s, o);
            if (t >= o) s += u;
        }
        ws[t] = s;
    }
    __syncthreads();
    int off = (w > 0) ? ws[w - 1] : 0;
    cum[b * Sv + t] = v + off;
}

// ---------------- frame -> source index ----------------
__global__ void __launch_bounds__(256)
idx_k(const int* __restrict__ cum, int* __restrict__ idx)
{
    int b = blockIdx.y;
    int t = blockIdx.x * 256 + threadIdx.x;
    const int* c = cum + b * Sv;
    int total = c[Sv - 1];
    int lo = 0, hi = Sv;
    while (lo < hi) { int mid = (lo + hi) >> 1; if (c[mid] <= t) lo = mid + 1; else hi = mid; }
    int ix = lo > (Sv - 1) ? (Sv - 1) : lo;
    idx[b * Tv + t] = (t < total) ? ix : -1;
}

// ---------------- mel for invalid frames ----------------
__global__ void __launch_bounds__(256)
melinv_k(const float* __restrict__ b1, const float* __restrict__ W2,
         const float* __restrict__ b2, float* __restrict__ inv)
{
    __shared__ float sbuf[8];
    int nm = blockIdx.x, tid = threadIdx.x;
    float v = 0.f;
    for (int f = tid; f < FFv; f += 256) {
        float r = b1[f]; r = r > 0.f ? r : 0.f;
        v += r * W2[(size_t)f * NMv + nm];
    }
    v = blk_sum(v, sbuf);
    if (tid == 0) inv[nm] = v + b2[nm];
}

// ---------------- gather mel rows into [B, NM, T] ----------------
__global__ void __launch_bounds__(256)
gather_k(const int* __restrict__ idx, const float* __restrict__ mels,
         const float* __restrict__ inv, float* __restrict__ mel)
{
    int t = blockIdx.x * 256 + threadIdx.x;
    int bn = blockIdx.y;
    int b = bn / NMv, nm = bn % NMv;
    int iv = idx[b * Tv + t];
    mel[(size_t)bn * Tv + t] =
        (iv < 0) ? inv[nm] : mels[((size_t)b * Sv + iv) * NMv + nm];
}

// ---------------- host launcher ----------------
static inline int gsmem(int nt) { return 2 * (2 * 128 * 80 + nt * 80); }

extern "C" void kernel_launch(void* const* d_in, const int* in_sizes, int n_in,
                              void* d_out, int out_size)
{
    const int*   ids    = (const int*)  d_in[0];
    const int*   lens   = (const int*)  d_in[1];
    const float* emb    = (const float*)d_in[3];
    const float* pe     = (const float*)d_in[4];
    const float* Wqkv   = (const float*)d_in[5];
    const float* bqkv   = (const float*)d_in[6];
    const float* Wo     = (const float*)d_in[7];
    const float* bo     = (const float*)d_in[8];
    const float* ln1s   = (const float*)d_in[9];
    const float* ln1b   = (const float*)d_in[10];
    const float* ln2s   = (const float*)d_in[11];
    const float* ln2b   = (const float*)d_in[12];
    const float* W1     = (const float*)d_in[13];
    const float* b1     = (const float*)d_in[14];
    const float* W2     = (const float*)d_in[15];
    const float* b2     = (const float*)d_in[16];
    const float* melW1  = (const float*)d_in[17];
    const float* melb1  = (const float*)d_in[18];
    const float* melW2  = (const float*)d_in[19];
    const float* melb2  = (const float*)d_in[20];
    const float* durW1  = (const float*)d_in[21];
    const float* durb1  = (const float*)d_in[22];
    const float* durW2  = (const float*)d_in[23];
    const float* durb2  = (const float*)d_in[24];

    float* out     = (float*)d_out;
    float* out_mel = out;
    float* out_dur = out + (size_t)Bv * NMv * Tv;
    float* out_enc = out_dur + (size_t)Bv * Sv;

    float *x, *qkv, *attn, *tmp, *big, *durh, *mels, *inv;
    int *cum, *idxp;
    __half *qkvT, *WoT, *W1T, *W2T, *m1T, *m2T, *d1T;
    cudaGetSymbolAddress((void**)&x,    g_x);
    cudaGetSymbolAddress((void**)&qkv,  g_qkv);
    cudaGetSymbolAddress((void**)&attn, g_attn);
    cudaGetSymbolAddress((void**)&tmp,  g_tmp);
    cudaGetSymbolAddress((void**)&big,  g_big);
    cudaGetSymbolAddress((void**)&durh, g_durh);
    cudaGetSymbolAddress((void**)&mels, g_mels);
    cudaGetSymbolAddress((void**)&inv,  g_inv);
    cudaGetSymbolAddress((void**)&cum,  g_cum);
    cudaGetSymbolAddress((void**)&idxp, g_idx);
    cudaGetSymbolAddress((void**)&qkvT, g_qkvT);
    cudaGetSymbolAddress((void**)&WoT,  g_WoT);
    cudaGetSymbolAddress((void**)&W1T,  g_W1T);
    cudaGetSymbolAddress((void**)&W2T,  g_W2T);
    cudaGetSymbolAddress((void**)&m1T,  g_m1T);
    cudaGetSymbolAddress((void**)&m2T,  g_m2T);
    cudaGetSymbolAddress((void**)&d1T,  g_d1T);

    cudaFuncSetAttribute(fattn_k, cudaFuncAttributeMaxDynamicSharedMemorySize, SM_ATT);
    const int sm64 = gsmem(64), sm128 = gsmem(128);
    cudaFuncSetAttribute(mgemm_k<64,1>,  cudaFuncAttributeMaxDynamicSharedMemorySize, sm64);
    cudaFuncSetAttribute(mgemm_k<64,2>,  cudaFuncAttributeMaxDynamicSharedMemorySize, sm64);
    cudaFuncSetAttribute(mgemm_k<128,2>, cudaFuncAttributeMaxDynamicSharedMemorySize, sm128);

    dim3 tb(32, 8);
    tsplit_k<<<dim3(48, 16, Lv), tb>>>(Wqkv,  qkvT, Dv, 3 * Dv);
    tsplit_k<<<dim3(16, 16, Lv), tb>>>(Wo,    WoT,  Dv, Dv);
    tsplit_k<<<dim3(64, 16, Lv), tb>>>(W1,    W1T,  Dv, FFv);
    tsplit_k<<<dim3(16, 64, Lv), tb>>>(W2,    W2T,  FFv, Dv);
    tsplit_k<<<dim3(64, 16, 1),  tb>>>(melW1, m1T,  Dv, FFv);
    tsplit_k<<<dim3(3,  64, 1),  tb>>>(melW2, m2T,  FFv, NMv);
    tsplit_k<<<dim3(8,  16, 1),  tb>>>(durW1, d1T,  Dv, 256);

    embed_k<<<NTOK, 128>>>(ids, emb, pe, x);

    for (int l = 0; l < Lv; l++) {
        mgemm_k<64,1><<<dim3(24, 32), 256, sm64>>>(
            x, qkvT + (size_t)l * 3 * Dv * Dv, bqkv + l * 3 * Dv, qkv, NTOK, 3 * Dv, Dv);
        fattn_k<<<dim3(Hv, Bv), 256, SM_ATT>>>(qkv, lens, attn);
        mgemm_k<64,1><<<dim3(8, 32), 256, sm64>>>(
            attn, WoT + (size_t)l * Dv * Dv, bo + l * Dv, tmp, NTOK, Dv, Dv);
        add_ln_k<<<NTOK, 128>>>(x, tmp, ln1s + l * Dv, ln1b + l * Dv, x);
        mgemm_k<128,2><<<dim3(16, 32), 256, sm128>>>(
            x, W1T + (size_t)l * FFv * Dv, b1 + l * FFv, big, NTOK, FFv, Dv);
        mgemm_k<64,1><<<dim3(8, 32), 256, sm64>>>(
            big, W2T + (size_t)l * Dv * FFv, b2 + l * Dv, tmp, NTOK, Dv, FFv);
        add_ln_k<<<NTOK, 128>>>(x, tmp, ln2s + l * Dv, ln2b + l * Dv, x);
    }

    cudaMemcpyAsync(out_enc, x, (size_t)NTOK * Dv * sizeof(float),
                    cudaMemcpyDeviceToDevice);

    // duration head
    mgemm_k<64,2><<<dim3(4, 32), 256, sm64>>>(x, d1T, durb1, durh, NTOK, 256, Dv);
    dur_head_k<<<NTOK, 256>>>(durh, durW2, durb2, out_dur);
    cumsum_k<<<Bv, 256>>>(out_dur, cum);

    // mel head on source tokens (gather commutes with row-wise MLP)
    mgemm_k<128,2><<<dim3(16, 32), 256, sm128>>>(x, m1T, melb1, big, NTOK, FFv, Dv);
    mgemm_k<64,1><<<dim3(2, 32), 256, sm64>>>(big, m2T, melb2, mels, NTOK, NMv, FFv);
    melinv_k<<<NMv, 256>>>(melb1, melW2, melb2, inv);

    idx_k<<<dim3(Tv / 256, Bv), 256>>>(cum, idxp);
    gather_k<<<dim3(Tv / 256, Bv * NMv), 256>>>(idxp, mels, inv, out_mel);
}

// round 9
// speedup vs baseline: 2.1681x; 1.0567x over previous
#include <cuda_runtime.h>
#include <cuda_fp16.h>
#include <math.h>
#include <stdint.h>

// ---------------- problem constants ----------------
#define Bv   16
#define Sv   256
#define Tv   2048
#define Dv   512
#define Hv   8
#define DHv  64
#define Lv   6
#define FFv  2048
#define NMv  80
#define NTOK (Bv*Sv)            // 4096 tokens

// ---------------- scratch (no allocs allowed) ----------------
__device__ float g_x   [NTOK*Dv];
__device__ float g_qkv [NTOK*3*Dv];
__device__ float g_attn[NTOK*Dv];
__device__ float g_tmp [NTOK*Dv];
__device__ float g_big [NTOK*FFv];
__device__ float g_durh[NTOK*256];
__device__ float g_mels[NTOK*NMv];
__device__ float g_inv [NMv];
__device__ int   g_cum [Bv*Sv];
__device__ int   g_idx [Bv*Tv];
// transposed weights ([N,K] K-major, single fp16)
__device__ __half g_qkvT[Lv*3*Dv*Dv];
__device__ __half g_WoT [Lv*Dv*Dv];
__device__ __half g_W1T [Lv*FFv*Dv];
__device__ __half g_W2T [Lv*Dv*FFv];
__device__ __half g_m1T [FFv*Dv];
__device__ __half g_m2T [NMv*FFv];
__device__ __half g_d1T [256*Dv];

// ---------------- low-level helpers ----------------
__device__ __forceinline__ uint32_t smem_u32(const void* p) {
    uint32_t a;
    asm("{ .reg .u64 t; cvta.to.shared.u64 t, %1; cvt.u32.u64 %0, t; }" : "=r"(a) : "l"(p));
    return a;
}
__device__ __forceinline__ void ldsm4(uint32_t& a0, uint32_t& a1, uint32_t& a2,
                                      uint32_t& a3, uint32_t addr) {
    asm volatile("ldmatrix.sync.aligned.m8n8.x4.shared.b16 {%0,%1,%2,%3}, [%4];"
                 : "=r"(a0), "=r"(a1), "=r"(a2), "=r"(a3) : "r"(addr));
}
__device__ __forceinline__ void ldsm2(uint32_t& b0, uint32_t& b1, uint32_t addr) {
    asm volatile("ldmatrix.sync.aligned.m8n8.x2.shared.b16 {%0,%1}, [%2];"
                 : "=r"(b0), "=r"(b1) : "r"(addr));
}
__device__ __forceinline__ void mma_f16(float* c, const uint32_t* a,
                                        uint32_t b0, uint32_t b1) {
    asm volatile("mma.sync.aligned.m16n8k16.row.col.f32.f16.f16.f32 "
                 "{%0,%1,%2,%3}, {%4,%5,%6,%7}, {%8,%9}, {%0,%1,%2,%3};"
                 : "+f"(c[0]), "+f"(c[1]), "+f"(c[2]), "+f"(c[3])
                 : "r"(a[0]), "r"(a[1]), "r"(a[2]), "r"(a[3]), "r"(b0), "r"(b1));
}
__device__ __forceinline__ void cpa16(uint32_t dst, const void* src, int sz) {
    asm volatile("cp.async.cg.shared.global [%0], [%1], 16, %2;"
                 :: "r"(dst), "l"(src), "r"(sz) : "memory");
}
#define CPA_COMMIT() asm volatile("cp.async.commit_group;" ::: "memory")
#define CPA_WAIT1()  asm volatile("cp.async.wait_group 1;" ::: "memory")

// split two fp32 into packed fp16x2 hi + fp16x2 lo
__device__ __forceinline__ void split2h(float x, float y, uint32_t& hi, uint32_t& lo) {
    __half2 h = __floats2half2_rn(x, y);
    float hx = __low2float(h);
    float hy = __high2float(h);
    __half2 l2 = __floats2half2_rn(x - hx, y - hy);
    hi = *(uint32_t*)&h;
    lo = *(uint32_t*)&l2;
}
__device__ __forceinline__ uint32_t packh2(float x, float y) {
    __half2 h = __floats2half2_rn(x, y);
    return *(uint32_t*)&h;
}

// ================= split-fp16 mma.sync GEMM (2-term, 3-stage, 1 sync/iter) ======
#define RSB     80u
#define TILE_A  (128u*RSB)

template<int NT_, int EPI>
__global__ void __launch_bounds__(256, 1)
mgemm_k(const float* __restrict__ A,
        const __half* __restrict__ Bt,
        const float* __restrict__ bias, float* __restrict__ C,
        int M, int N, int K)
{
    constexpr uint32_t TILE_BN = (uint32_t)NT_ * RSB;
    constexpr uint32_t STAGE = 2u * TILE_A + TILE_BN;   // A_hi | A_lo | B
    constexpr int NI = NT_ / 16;
    extern __shared__ char smem[];
    uint32_t sb = smem_u32(smem);
    int tid = threadIdx.x, wid = tid >> 5, l = tid & 31;
    int m0 = blockIdx.y * 128, n0 = blockIdx.x * NT_;
    int wm = (wid & 3) * 32, wn = (wid >> 2) * (NT_ / 2);

    float acc[2][NI][4];
    #pragma unroll
    for (int mi = 0; mi < 2; mi++)
        #pragma unroll
        for (int ni = 0; ni < NI; ni++)
            #pragma unroll
            for (int q = 0; q < 4; q++) acc[mi][ni][q] = 0.f;

    int ar_ = tid >> 3, ac_ = tid & 7;    // A: 32 rows x 8 col-groups (x4 rows)
    int brow = tid >> 2, bch = tid & 3;   // B: cp.async row/chunk

    float4 ard[4];
    const int NT = K / 32;

    auto loadA = [&](int kt) {
        int k0 = kt * 32;
        #pragma unroll
        for (int i = 0; i < 4; i++)
            ard[i] = *(const float4*)(A + (size_t)(m0 + ar_ + i * 32) * K + k0 + ac_ * 4);
    };
    auto storeA = [&](int s) {
        char* dst = smem + (uint32_t)s * STAGE;
        #pragma unroll
        for (int i = 0; i < 4; i++) {
            uint32_t h0, h1, l0, l1;
            split2h(ard[i].x, ard[i].y, h0, l0);
            split2h(ard[i].z, ard[i].w, h1, l1);
            uint32_t off = (uint32_t)(ar_ + i * 32) * RSB + ac_ * 8u;
            *(uint2*)(dst + off)          = make_uint2(h0, h1);
            *(uint2*)(dst + TILE_A + off) = make_uint2(l0, l1);
        }
    };
    auto cpaB = [&](int kt, int s) {
        uint32_t bbase = sb + (uint32_t)s * STAGE + 2u * TILE_A;
        int k0 = kt * 32;
        #pragma unroll
        for (int i = 0; i < NT_ / 64; i++) {
            int row = brow + i * 64;
            int nr = n0 + row;
            int ok  = (nr < N) ? 16 : 0;
            int nrc = (nr < N) ? nr : 0;
            cpa16(bbase + (uint32_t)row * RSB + (uint32_t)bch * 16u,
                  Bt + (size_t)nrc * K + k0 + bch * 8, ok);
        }
    };

    // prologue: stages 0, 1
    loadA(0); storeA(0); cpaB(0, 0); CPA_COMMIT();
    if (NT > 1) { loadA(1); storeA(1); cpaB(1, 1); }
    CPA_COMMIT();

    uint32_t aoff = (uint32_t)(wm + (l & 15)) * RSB + (uint32_t)(l >> 4) * 16u;
    uint32_t boff = (uint32_t)(wn + (l & 7)) * RSB + (uint32_t)((l >> 3) & 1) * 16u;

    int s_cur = 0, s_pf = 2;   // stage being computed / stage being prefetched
    for (int kt = 0; kt < NT; kt++) {
        CPA_WAIT1();
        __syncthreads();
        bool pf = (kt + 2 < NT);
        if (pf) { loadA(kt + 2); cpaB(kt + 2, s_pf); }
        CPA_COMMIT();

        // compute on stage s_cur
        {
            uint32_t aH_ = sb + (uint32_t)s_cur * STAGE;
            uint32_t aL_ = aH_ + TILE_A;
            uint32_t bB_ = aH_ + 2 * TILE_A;
            #pragma unroll
            for (int ks = 0; ks < 2; ks++) {
                uint32_t ah[2][4], al[2][4];
                #pragma unroll
                for (int mi = 0; mi < 2; mi++) {
                    uint32_t ad = aoff + (uint32_t)mi * 16u * RSB + (uint32_t)ks * 32u;
                    ldsm4(ah[mi][0], ah[mi][1], ah[mi][2], ah[mi][3], aH_ + ad);
                    ldsm4(al[mi][0], al[mi][1], al[mi][2], al[mi][3], aL_ + ad);
                }
                #pragma unroll
                for (int ni = 0; ni < NI; ni++) {
                    uint32_t bd = boff + (uint32_t)ni * 8u * RSB + (uint32_t)ks * 32u;
                    uint32_t b0, b1;
                    ldsm2(b0, b1, bB_ + bd);
                    #pragma unroll
                    for (int mi = 0; mi < 2; mi++) {
                        mma_f16(acc[mi][ni], ah[mi], b0, b1);
                        mma_f16(acc[mi][ni], al[mi], b0, b1);
                    }
                }
            }
        }
        if (pf) storeA(s_pf);
        s_cur = (s_cur == 2) ? 0 : s_cur + 1;
        s_pf  = (s_pf  == 2) ? 0 : s_pf  + 1;
    }

    // epilogue
    int r_lo = l >> 2, cpair = (l & 3) * 2;
    #pragma unroll
    for (int mi = 0; mi < 2; mi++) {
        int gr0 = m0 + wm + mi * 16 + r_lo;
        #pragma unroll
        for (int ni = 0; ni < NI; ni++) {
            int gc = n0 + wn + ni * 8 + cpair;
            if (gc < N) {
                float b0 = 0.f, b1 = 0.f;
                if (EPI >= 1) { b0 = bias[gc]; b1 = bias[gc + 1]; }
                float v0 = acc[mi][ni][0] + b0, v1 = acc[mi][ni][1] + b1;
                float v2 = acc[mi][ni][2] + b0, v3 = acc[mi][ni][3] + b1;
                if (EPI == 2) {
                    v0 = fmaxf(v0, 0.f); v1 = fmaxf(v1, 0.f);
                    v2 = fmaxf(v2, 0.f); v3 = fmaxf(v3, 0.f);
                }
                *(float2*)(C + (size_t)gr0 * N + gc)       = make_float2(v0, v1);
                *(float2*)(C + (size_t)(gr0 + 8) * N + gc) = make_float2(v2, v3);
            }
        }
    }
}

// ================= tensor-core flash attention (unchanged from R8) ==============
#define QROW 144u
#define VROW 528u
#define SM_QH 0u
#define SM_QL 36864u
#define SM_KH 73728u
#define SM_KL 110592u
#define SM_VT 147456u
#define SM_ATT (147456 + 64*528)

__global__ void __launch_bounds__(256, 1)
fattn_k(const float* __restrict__ qkv, const int* __restrict__ lens,
        float* __restrict__ o)
{
    extern __shared__ char smem[];
    uint32_t sb = smem_u32(smem);
    int h = blockIdx.x, b = blockIdx.y;
    int tid = threadIdx.x, wid = tid >> 5, l = tid & 31;
    int len = lens[b];

    {
        const float* base = qkv + (size_t)b * Sv * (3 * Dv);
        const float4* qrow = (const float4*)(base + (size_t)tid * 3 * Dv + h * DHv);
        const float4* krow = (const float4*)(base + (size_t)tid * 3 * Dv + Dv + h * DHv);
        const float4* vrow = (const float4*)(base + (size_t)tid * 3 * Dv + 2 * Dv + h * DHv);
        uint32_t qd = (uint32_t)tid * QROW;
        #pragma unroll
        for (int i = 0; i < 16; i++) {
            float4 q = qrow[i];
            q.x *= 0.125f; q.y *= 0.125f; q.z *= 0.125f; q.w *= 0.125f;
            uint32_t h0, h1, l0, l1;
            split2h(q.x, q.y, h0, l0);
            split2h(q.z, q.w, h1, l1);
            *(uint2*)(smem + qd + SM_QH + i * 8u) = make_uint2(h0, h1);
            *(uint2*)(smem + qd + SM_QL + i * 8u) = make_uint2(l0, l1);
            float4 k = krow[i];
            split2h(k.x, k.y, h0, l0);
            split2h(k.z, k.w, h1, l1);
            *(uint2*)(smem + qd + SM_KH + i * 8u) = make_uint2(h0, h1);
            *(uint2*)(smem + qd + SM_KL + i * 8u) = make_uint2(l0, l1);
            float4 v = vrow[i];
            __half* vt = (__half*)(smem + SM_VT);
            vt[(4*i+0) * (VROW/2) + tid] = __float2half_rn(v.x);
            vt[(4*i+1) * (VROW/2) + tid] = __float2half_rn(v.y);
            vt[(4*i+2) * (VROW/2) + tid] = __float2half_rn(v.z);
            vt[(4*i+3) * (VROW/2) + tid] = __float2half_rn(v.w);
        }
    }
    __syncthreads();

    int wq = wid * 32;
    float mrow[2][2], lrow[2][2];
    #pragma unroll
    for (int mi = 0; mi < 2; mi++) { mrow[mi][0] = -1e9f; mrow[mi][1] = -1e9f;
                                     lrow[mi][0] = 0.f;   lrow[mi][1] = 0.f; }
    float acc_o[2][8][4];
    #pragma unroll
    for (int mi = 0; mi < 2; mi++)
        #pragma unroll
        for (int ni = 0; ni < 8; ni++)
            #pragma unroll
            for (int q = 0; q < 4; q++) acc_o[mi][ni][q] = 0.f;

    for (int kc = 0; kc < 4; kc++) {
        int kbase = kc * 64;
        if (kbase >= len) break;

        float s_[2][8][4];
        #pragma unroll
        for (int mi = 0; mi < 2; mi++)
            #pragma unroll
            for (int ni = 0; ni < 8; ni++)
                #pragma unroll
                for (int q = 0; q < 4; q++) s_[mi][ni][q] = 0.f;

        #pragma unroll
        for (int kst = 0; kst < 4; kst++) {
            uint32_t qh[2][4], ql[2][4];
            #pragma unroll
            for (int mi = 0; mi < 2; mi++) {
                uint32_t ad = (uint32_t)(wq + mi * 16 + (l & 15)) * QROW
                            + (uint32_t)(l >> 4) * 16u + (uint32_t)kst * 32u;
                ldsm4(qh[mi][0], qh[mi][1], qh[mi][2], qh[mi][3], sb + SM_QH + ad);
                ldsm4(ql[mi][0], ql[mi][1], ql[mi][2], ql[mi][3], sb + SM_QL + ad);
            }
            #pragma unroll
            for (int ni = 0; ni < 8; ni++) {
                uint32_t kd = (uint32_t)(kbase + ni * 8 + (l & 7)) * QROW
                            + (uint32_t)((l >> 3) & 1) * 16u + (uint32_t)kst * 32u;
                uint32_t kh0, kh1, kl0, kl1;
                ldsm2(kh0, kh1, sb + SM_KH + kd);
                ldsm2(kl0, kl1, sb + SM_KL + kd);
                #pragma unroll
                for (int mi = 0; mi < 2; mi++) {
                    mma_f16(s_[mi][ni], qh[mi], kh0, kh1);
                    mma_f16(s_[mi][ni], ql[mi], kh0, kh1);
                    mma_f16(s_[mi][ni], qh[mi], kl0, kl1);
                }
            }
        }

        int kcol = kbase + (l & 3) * 2;
        #pragma unroll
        for (int mi = 0; mi < 2; mi++)
            #pragma unroll
            for (int ni = 0; ni < 8; ni++) {
                int k0 = kcol + ni * 8;
                if (k0 >= len)     { s_[mi][ni][0] = -1e9f; s_[mi][ni][2] = -1e9f; }
                if (k0 + 1 >= len) { s_[mi][ni][1] = -1e9f; s_[mi][ni][3] = -1e9f; }
            }

        #pragma unroll
        for (int mi = 0; mi < 2; mi++) {
            float cm0 = -1e9f, cm1 = -1e9f;
            #pragma unroll
            for (int ni = 0; ni < 8; ni++) {
                cm0 = fmaxf(cm0, fmaxf(s_[mi][ni][0], s_[mi][ni][1]));
                cm1 = fmaxf(cm1, fmaxf(s_[mi][ni][2], s_[mi][ni][3]));
            }
            cm0 = fmaxf(cm0, __shfl_xor_sync(0xffffffffu, cm0, 1));
            cm0 = fmaxf(cm0, __shfl_xor_sync(0xffffffffu, cm0, 2));
            cm1 = fmaxf(cm1, __shfl_xor_sync(0xffffffffu, cm1, 1));
            cm1 = fmaxf(cm1, __shfl_xor_sync(0xffffffffu, cm1, 2));
            float nm0 = fmaxf(mrow[mi][0], cm0);
            float nm1 = fmaxf(mrow[mi][1], cm1);
            float c0 = __expf(mrow[mi][0] - nm0);
            float c1 = __expf(mrow[mi][1] - nm1);
            float rs0 = 0.f, rs1 = 0.f;
            #pragma unroll
            for (int ni = 0; ni < 8; ni++) {
                s_[mi][ni][0] = __expf(s_[mi][ni][0] - nm0);
                s_[mi][ni][1] = __expf(s_[mi][ni][1] - nm0);
                s_[mi][ni][2] = __expf(s_[mi][ni][2] - nm1);
                s_[mi][ni][3] = __expf(s_[mi][ni][3] - nm1);
                rs0 += s_[mi][ni][0] + s_[mi][ni][1];
                rs1 += s_[mi][ni][2] + s_[mi][ni][3];
            }
            rs0 += __shfl_xor_sync(0xffffffffu, rs0, 1);
            rs0 += __shfl_xor_sync(0xffffffffu, rs0, 2);
            rs1 += __shfl_xor_sync(0xffffffffu, rs1, 1);
            rs1 += __shfl_xor_sync(0xffffffffu, rs1, 2);
            lrow[mi][0] = lrow[mi][0] * c0 + rs0;
            lrow[mi][1] = lrow[mi][1] * c1 + rs1;
            mrow[mi][0] = nm0; mrow[mi][1] = nm1;
            #pragma unroll
            for (int ni = 0; ni < 8; ni++) {
                acc_o[mi][ni][0] *= c0; acc_o[mi][ni][1] *= c0;
                acc_o[mi][ni][2] *= c1; acc_o[mi][ni][3] *= c1;
            }
        }

        #pragma unroll
        for (int kj = 0; kj < 4; kj++) {
            uint32_t pa[2][4];
            #pragma unroll
            for (int mi = 0; mi < 2; mi++) {
                pa[mi][0] = packh2(s_[mi][2*kj][0],   s_[mi][2*kj][1]);
                pa[mi][1] = packh2(s_[mi][2*kj][2],   s_[mi][2*kj][3]);
                pa[mi][2] = packh2(s_[mi][2*kj+1][0], s_[mi][2*kj+1][1]);
                pa[mi][3] = packh2(s_[mi][2*kj+1][2], s_[mi][2*kj+1][3]);
            }
            #pragma unroll
            for (int ni = 0; ni < 8; ni++) {
                uint32_t vd = (uint32_t)(ni * 8 + (l & 7)) * VROW
                            + (uint32_t)((l >> 3) & 1) * 16u
                            + (uint32_t)kbase * 2u + (uint32_t)kj * 32u;
                uint32_t v0, v1;
                ldsm2(v0, v1, sb + SM_VT + vd);
                #pragma unroll
                for (int mi = 0; mi < 2; mi++)
                    mma_f16(acc_o[mi][ni], pa[mi], v0, v1);
            }
        }
    }

    #pragma unroll
    for (int mi = 0; mi < 2; mi++) {
        float inv0 = (lrow[mi][0] > 0.f) ? 1.f / lrow[mi][0] : 0.f;
        float inv1 = (lrow[mi][1] > 0.f) ? 1.f / lrow[mi][1] : 0.f;
        int ra = wq + mi * 16 + (l >> 2);
        int rb = ra + 8;
        #pragma unroll
        for (int ni = 0; ni < 8; ni++) {
            int col = h * DHv + ni * 8 + (l & 3) * 2;
            *(float2*)(o + ((size_t)b * Sv + ra) * Dv + col) =
                make_float2(acc_o[mi][ni][0] * inv0, acc_o[mi][ni][1] * inv0);
            *(float2*)(o + ((size_t)b * Sv + rb) * Dv + col) =
                make_float2(acc_o[mi][ni][2] * inv1, acc_o[mi][ni][3] * inv1);
        }
    }
}

// ---------------- transpose + fp16 round ----------------
__global__ void __launch_bounds__(256)
tsplit_k(const float* __restrict__ in, __half* __restrict__ outH, int R, int C)
{
    __shared__ float t[32][33];
    size_t zo = (size_t)blockIdx.z * R * C;
    int c0 = blockIdx.x * 32, r0 = blockIdx.y * 32;
    int x = threadIdx.x, y = threadIdx.y;
    #pragma unroll
    for (int i = 0; i < 32; i += 8) {
        int r = r0 + y + i, c = c0 + x;
        if (r < R && c < C) t[y + i][x] = in[zo + (size_t)r * C + c];
    }
    __syncthreads();
    #pragma unroll
    for (int i = 0; i < 32; i += 8) {
        int c = c0 + y + i, r = r0 + x;
        if (c < C && r < R)
            outH[zo + (size_t)c * R + r] = __float2half_rn(t[x][y + i]);
    }
}

// ---------------- misc helpers ----------------
__device__ __forceinline__ float blk_sum(float v, float* sbuf) {
    __syncthreads();
    int lane = threadIdx.x & 31, w = threadIdx.x >> 5;
    #pragma unroll
    for (int o = 16; o; o >>= 1) v += __shfl_xor_sync(0xffffffffu, v, o);
    if (lane == 0) sbuf[w] = v;
    __syncthreads();
    int nw = blockDim.x >> 5;
    float r = (threadIdx.x < nw) ? sbuf[threadIdx.x] : 0.f;
    if (w == 0) {
        #pragma unroll
        for (int o = 16; o; o >>= 1) r += __shfl_xor_sync(0xffffffffu, r, o);
        if (lane == 0) sbuf[0] = r;
    }
    __syncthreads();
    return sbuf[0];
}

// ---------------- embedding + positional encoding ----------------
__global__ void __launch_bounds__(128)
embed_k(const int* __restrict__ ids, const float* __restrict__ emb,
        const float* __restrict__ pe, float* __restrict__ x)
{
    int token = blockIdx.x;
    int tid = threadIdx.x;
    int s = token % Sv;
    int id = ids[token];
    float4 e = ((const float4*)(emb + (size_t)id * Dv))[tid];
    float4 p = ((const float4*)(pe + (size_t)s * Dv))[tid];
    e.x += p.x; e.y += p.y; e.z += p.z; e.w += p.w;
    ((float4*)(x + (size_t)token * Dv))[tid] = e;
}

// ---------------- residual add + LayerNorm ----------------
__global__ void __launch_bounds__(128)
add_ln_k(const float* __restrict__ x, const float* __restrict__ y,
         const float* __restrict__ s, const float* __restrict__ bta,
         float* __restrict__ out)
{
    __shared__ float sbuf[8];
    int row = blockIdx.x, tid = threadIdx.x;
    float4 v = ((const float4*)(x + (size_t)row * Dv))[tid];
    float4 w = ((const float4*)(y + (size_t)row * Dv))[tid];
    v.x += w.x; v.y += w.y; v.z += w.z; v.w += w.w;

    float sum = blk_sum(v.x + v.y + v.z + v.w, sbuf);
    float mean = sum * (1.f / Dv);
    float dx = v.x - mean, dy = v.y - mean, dz = v.z - mean, dw = v.w - mean;
    float var = blk_sum(dx*dx + dy*dy + dz*dz + dw*dw, sbuf) * (1.f / Dv);
    float rstd = rsqrtf(var + 1e-5f);

    float4 sv = ((const float4*)s)[tid];
    float4 bv = ((const float4*)bta)[tid];
    float4 r;
    r.x = dx * rstd * sv.x + bv.x;
    r.y = dy * rstd * sv.y + bv.y;
    r.z = dz * rstd * sv.z + bv.z;
    r.w = dw * rstd * sv.w + bv.w;
    ((float4*)(out + (size_t)row * Dv))[tid] = r;
}

// ---------------- duration head ----------------
__global__ void __launch_bounds__(256)
dur_head_k(const float* __restrict__ durh, const float* __restrict__ W2,
           const float* __restrict__ b2, float* __restrict__ dur)
{
    __shared__ float sbuf[8];
    int row = blockIdx.x, tid = threadIdx.x;
    float v = durh[(size_t)row * 256 + tid] * W2[tid];
    v = blk_sum(v, sbuf);
    if (tid == 0) {
        float z = v + b2[0];
        dur[row] = (z > 20.f) ? z : log1pf(expf(z));
    }
}

// ---------------- parallel cumulative durations ----------------
__global__ void __launch_bounds__(256)
cumsum_k(const float* __restrict__ dur, int* __restrict__ cum)
{
    __shared__ int ws[8];
    int b = blockIdx.x, t = threadIdx.x;
    int lane = t & 31, w = t >> 5;
    int d = (int)rintf(dur[b * Sv + t]);
    if (d < 1) d = 1;
    int v = d;
    #pragma unroll
    for (int o = 1; o < 32; o <<= 1) {
        int u = __shfl_up_sync(0xffffffffu, v, o);
        if (lane >= o) v += u;
    }
    if (lane == 31) ws[w] = v;
    __syncthreads();
    if (t < 8) {
        int s = ws[t];
        #pragma unroll
        for (int o = 1; o < 8; o <<= 1) {
            int u = __shfl_up_sync(0x000000ffu, s, o);
            if (t >= o) s += u;
        }
        ws[t] = s;
    }
    __syncthreads();
    int off = (w > 0) ? ws[w - 1] : 0;
    cum[b * Sv + t] = v + off;
}

// ---------------- frame -> source index ----------------
__global__ void __launch_bounds__(256)
idx_k(const int* __restrict__ cum, int* __restrict__ idx)
{
    int b = blockIdx.y;
    int t = blockIdx.x * 256 + threadIdx.x;
    const int* c = cum + b * Sv;
    int total = c[Sv - 1];
    int lo = 0, hi = Sv;
    while (lo < hi) { int mid = (lo + hi) >> 1; if (c[mid] <= t) lo = mid + 1; else hi = mid; }
    int ix = lo > (Sv - 1) ? (Sv - 1) : lo;
    idx[b * Tv + t] = (t < total) ? ix : -1;
}

// ---------------- mel for invalid frames ----------------
__global__ void __launch_bounds__(256)
melinv_k(const float* __restrict__ b1, const float* __restrict__ W2,
         const float* __restrict__ b2, float* __restrict__ inv)
{
    __shared__ float sbuf[8];
    int nm = blockIdx.x, tid = threadIdx.x;
    float v = 0.f;
    for (int f = tid; f < FFv; f += 256) {
        float r = b1[f]; r = r > 0.f ? r : 0.f;
        v += r * W2[(size_t)f * NMv + nm];
    }
    v = blk_sum(v, sbuf);
    if (tid == 0) inv[nm] = v + b2[nm];
}

// ---------------- gather mel rows into [B, NM, T] ----------------
__global__ void __launch_bounds__(256)
gather_k(const int* __restrict__ idx, const float* __restrict__ mels,
         const float* __restrict__ inv, float* __restrict__ mel)
{
    int t = blockIdx.x * 256 + threadIdx.x;
    int bn = blockIdx.y;
    int b = bn / NMv, nm = bn % NMv;
    int iv = idx[b * Tv + t];
    mel[(size_t)bn * Tv + t] =
        (iv < 0) ? inv[nm] : mels[((size_t)b * Sv + iv) * NMv + nm];
}

// ---------------- host launcher ----------------
static inline int gsmem(int nt) { return 3 * (2 * 128 * 80 + nt * 80); }

extern "C" void kernel_launch(void* const* d_in, const int* in_sizes, int n_in,
                              void* d_out, int out_size)
{
    const int*   ids    = (const int*)  d_in[0];
    const int*   lens   = (const int*)  d_in[1];
    const float* emb    = (const float*)d_in[3];
    const float* pe     = (const float*)d_in[4];
    const float* Wqkv   = (const float*)d_in[5];
    const float* bqkv   = (const float*)d_in[6];
    const float* Wo     = (const float*)d_in[7];
    const float* bo     = (const float*)d_in[8];
    const float* ln1s   = (const float*)d_in[9];
    const float* ln1b   = (const float*)d_in[10];
    const float* ln2s   = (const float*)d_in[11];
    const float* ln2b   = (const float*)d_in[12];
    const float* W1     = (const float*)d_in[13];
    const float* b1     = (const float*)d_in[14];
    const float* W2     = (const float*)d_in[15];
    const float* b2     = (const float*)d_in[16];
    const float* melW1  = (const float*)d_in[17];
    const float* melb1  = (const float*)d_in[18];
    const float* melW2  = (const float*)d_in[19];
    const float* melb2  = (const float*)d_in[20];
    const float* durW1  = (const float*)d_in[21];
    const float* durb1  = (const float*)d_in[22];
    const float* durW2  = (const float*)d_in[23];
    const float* durb2  = (const float*)d_in[24];

    float* out     = (float*)d_out;
    float* out_mel = out;
    float* out_dur = out + (size_t)Bv * NMv * Tv;
    float* out_enc = out_dur + (size_t)Bv * Sv;

    float *x, *qkv, *attn, *tmp, *big, *durh, *mels, *inv;
    int *cum, *idxp;
    __half *qkvT, *WoT, *W1T, *W2T, *m1T, *m2T, *d1T;
    cudaGetSymbolAddress((void**)&x,    g_x);
    cudaGetSymbolAddress((void**)&qkv,  g_qkv);
    cudaGetSymbolAddress((void**)&attn, g_attn);
    cudaGetSymbolAddress((void**)&tmp,  g_tmp);
    cudaGetSymbolAddress((void**)&big,  g_big);
    cudaGetSymbolAddress((void**)&durh, g_durh);
    cudaGetSymbolAddress((void**)&mels, g_mels);
    cudaGetSymbolAddress((void**)&inv,  g_inv);
    cudaGetSymbolAddress((void**)&cum,  g_cum);
    cudaGetSymbolAddress((void**)&idxp, g_idx);
    cudaGetSymbolAddress((void**)&qkvT, g_qkvT);
    cudaGetSymbolAddress((void**)&WoT,  g_WoT);
    cudaGetSymbolAddress((void**)&W1T,  g_W1T);
    cudaGetSymbolAddress((void**)&W2T,  g_W2T);
    cudaGetSymbolAddress((void**)&m1T,  g_m1T);
    cudaGetSymbolAddress((void**)&m2T,  g_m2T);
    cudaGetSymbolAddress((void**)&d1T,  g_d1T);

    cudaFuncSetAttribute(fattn_k, cudaFuncAttributeMaxDynamicSharedMemorySize, SM_ATT);
    const int sm64 = gsmem(64), sm128 = gsmem(128);
    cudaFuncSetAttribute(mgemm_k<64,1>,  cudaFuncAttributeMaxDynamicSharedMemorySize, sm64);
    cudaFuncSetAttribute(mgemm_k<64,2>,  cudaFuncAttributeMaxDynamicSharedMemorySize, sm64);
    cudaFuncSetAttribute(mgemm_k<128,2>, cudaFuncAttributeMaxDynamicSharedMemorySize, sm128);

    dim3 tb(32, 8);
    tsplit_k<<<dim3(48, 16, Lv), tb>>>(Wqkv,  qkvT, Dv, 3 * Dv);
    tsplit_k<<<dim3(16, 16, Lv), tb>>>(Wo,    WoT,  Dv, Dv);
    tsplit_k<<<dim3(64, 16, Lv), tb>>>(W1,    W1T,  Dv, FFv);
    tsplit_k<<<dim3(16, 64, Lv), tb>>>(W2,    W2T,  FFv, Dv);
    tsplit_k<<<dim3(64, 16, 1),  tb>>>(melW1, m1T,  Dv, FFv);
    tsplit_k<<<dim3(3,  64, 1),  tb>>>(melW2, m2T,  FFv, NMv);
    tsplit_k<<<dim3(8,  16, 1),  tb>>>(durW1, d1T,  Dv, 256);

    embed_k<<<NTOK, 128>>>(ids, emb, pe, x);

    for (int l = 0; l < Lv; l++) {
        mgemm_k<64,1><<<dim3(24, 32), 256, sm64>>>(
            x, qkvT + (size_t)l * 3 * Dv * Dv, bqkv + l * 3 * Dv, qkv, NTOK, 3 * Dv, Dv);
        fattn_k<<<dim3(Hv, Bv), 256, SM_ATT>>>(qkv, lens, attn);
        mgemm_k<64,1><<<dim3(8, 32), 256, sm64>>>(
            attn, WoT + (size_t)l * Dv * Dv, bo + l * Dv, tmp, NTOK, Dv, Dv);
        add_ln_k<<<NTOK, 128>>>(x, tmp, ln1s + l * Dv, ln1b + l * Dv, x);
        mgemm_k<128,2><<<dim3(16, 32), 256, sm128>>>(
            x, W1T + (size_t)l * FFv * Dv, b1 + l * FFv, big, NTOK, FFv, Dv);
        mgemm_k<64,1><<<dim3(8, 32), 256, sm64>>>(
            big, W2T + (size_t)l * Dv * FFv, b2 + l * Dv, tmp, NTOK, Dv, FFv);
        add_ln_k<<<NTOK, 128>>>(x, tmp, ln2s + l * Dv, ln2b + l * Dv, x);
    }

    cudaMemcpyAsync(out_enc, x, (size_t)NTOK * Dv * sizeof(float),
                    cudaMemcpyDeviceToDevice);

    // duration head
    mgemm_k<64,2><<<dim3(4, 32), 256, sm64>>>(x, d1T, durb1, durh, NTOK, 256, Dv);
    dur_head_k<<<NTOK, 256>>>(durh, durW2, durb2, out_dur);
    cumsum_k<<<Bv, 256>>>(out_dur, cum);

    // mel head on source tokens (gather commutes with row-wise MLP)
    mgemm_k<128,2><<<dim3(16, 32), 256, sm128>>>(x, m1T, melb1, big, NTOK, FFv, Dv);
    mgemm_k<64,1><<<dim3(2, 32), 256, sm64>>>(big, m2T, melb2, mels, NTOK, NMv, FFv);
    melinv_k<<<NMv, 256>>>(melb1, melW2, melb2, inv);

    idx_k<<<dim3(Tv / 256, Bv), 256>>>(cum, idxp);
    gather_k<<<dim3(Tv / 256, Bv * NMv), 256>>>(idxp, mels, inv, out_mel);
}